// round 13
// baseline (speedup 1.0000x reference)
#include <cuda_runtime.h>
#include <cuda_fp16.h>
#include <math.h>
#include <stdint.h>

#define BB 32
#define CC 256
#define NN 3136
#define OUTC 32896            // 256*257/2
#define MATSZ (BB*CC*CC)

#define CHK 32
#define STG64 16384           // gram stage: A(8K)+B(8K)
#define SMEM64 49152          // 2 stages + room for mirror-transpose buffer
#define STG32 12288           // ns stage: A(8K)+B(4K)
#define SMEM32 (3*STG32)      // 36864
#define SSCALE 64.0f
#define INVS2 (1.0f/(SSCALE*SSCALE))
#define MP 72                 // transpose-buffer pitch in halves

// gram: 10 upper 64x64 tiles
__device__ __constant__ int c_TI[10] = {0,0,0,0,1,1,1,2,2,3};
__device__ __constant__ int c_TJ[10] = {0,1,2,3,1,2,3,2,3,3};
// ns: 20 tiles 64x32 with j*32 >= i*64
__device__ __constant__ int c_SI[20] = {0,0,0,0,0,0,0,0, 1,1,1,1,1,1, 2,2,2,2, 3,3};
__device__ __constant__ int c_SJ[20] = {0,1,2,3,4,5,6,7, 2,3,4,5,6,7, 4,5,6,7, 6,7};

// ---------------- scratch: matrices stored as hi/lo fp16 pairs ----------------
// slots: A=0 B0=1 B1=2 Y0=3 Y1=4 Z0=5 Z1=6
__device__ __align__(16) __half g_H[7*MATSZ];
__device__ __align__(16) __half g_L[7*MATSZ];
__device__ float g_s[BB*CC];
__device__ float g_q[BB*CC];
__device__ float g_tr[BB];

// ---------------- primitives ----------------
__device__ __forceinline__ uint32_t smem_u32(const void* p) {
    uint32_t a;
    asm("{ .reg .u64 t; cvta.to.shared.u64 t, %1; cvt.u32.u64 %0, t; }" : "=r"(a) : "l"(p));
    return a;
}

__device__ __forceinline__ void mma16(float* c, const unsigned* a, const unsigned* b) {
    asm volatile(
        "mma.sync.aligned.m16n8k16.row.col.f32.f16.f16.f32 "
        "{%0,%1,%2,%3}, {%4,%5,%6,%7}, {%8,%9}, {%0,%1,%2,%3};"
        : "+f"(c[0]), "+f"(c[1]), "+f"(c[2]), "+f"(c[3])
        : "r"(a[0]), "r"(a[1]), "r"(a[2]), "r"(a[3]), "r"(b[0]), "r"(b[1]));
}

__device__ __forceinline__ void ldm4(unsigned r[4], uint32_t a) {
    asm volatile("ldmatrix.sync.aligned.m8n8.x4.shared.b16 {%0,%1,%2,%3}, [%4];"
                 : "=r"(r[0]), "=r"(r[1]), "=r"(r[2]), "=r"(r[3]) : "r"(a));
}

#define CP16(dst, src) \
    asm volatile("cp.async.cg.shared.global [%0], [%1], 16;" :: "r"(dst), "l"(src))
#define CP_COMMIT() asm volatile("cp.async.commit_group;" ::: "memory")
#define CP_WAIT1() asm volatile("cp.async.wait_group 1;" ::: "memory")

__device__ __forceinline__ void split_pair(float v0, float v1, unsigned& hi, unsigned& lo) {
    float s0 = v0 * SSCALE, s1 = v1 * SSCALE;
    __half h0 = __float2half_rn(s0), h1 = __float2half_rn(s1);
    __half l0 = __float2half_rn(s0 - __half2float(h0));
    __half l1 = __float2half_rn(s1 - __half2float(h1));
    __half2 hh = __halves2half2(h0, h1), ll = __halves2half2(l0, l1);
    hi = *(unsigned*)&hh;
    lo = *(unsigned*)&ll;
}

// ================= 64x64 gram path: f32 load + split-on-store =================
// stage layout (matches ldmatrix consumer): 64 rows x 128B [hi 64B | lo 64B], g ^= row&7
__device__ __forceinline__ void cvt_store16(char* matBase, int rr, int half, const float4* v) {
    const float* f = (const float*)v;
#pragma unroll
    for (int j = 0; j < 2; ++j) {
        unsigned h[4], l[4];
#pragma unroll
        for (int e = 0; e < 4; ++e)
            split_pair(f[8 * j + 2 * e], f[8 * j + 2 * e + 1], h[e], l[e]);
        int g = half * 2 + j;
        char* rowb = matBase + rr * 128;
        *(uint4*)(rowb + ((g ^ (rr & 7)) << 4)) = make_uint4(h[0], h[1], h[2], h[3]);
        *(uint4*)(rowb + (((g + 4) ^ (rr & 7)) << 4)) = make_uint4(l[0], l[1], l[2], l[3]);
    }
}

__device__ __forceinline__ void compute_chunk64(uint32_t stBase, float acc[2][4][4],
                                                int wm, int wn, int lane) {
    int lr = lane & 7;
    int lt8 = (lane >> 3) & 1;
    int lkh = (lane >> 4) & 1;
    uint32_t aL = stBase + (wm * 32 + lt8 * 8 + lr) * 128;
    uint32_t bL = stBase + 8192 + (wn * 32 + lkh * 8 + lr) * 128;
#pragma unroll
    for (int ks = 0; ks < 2; ++ks) {
        unsigned ah[2][4], al[2][4], bh[2][4], bl[2][4];
        int gA = ks * 2 + lkh, gB = ks * 2 + lt8;
        ldm4(ah[0], aL + ((gA ^ lr) << 4));
        ldm4(ah[1], aL + 2048 + ((gA ^ lr) << 4));
        ldm4(al[0], aL + (((gA + 4) ^ lr) << 4));
        ldm4(al[1], aL + 2048 + (((gA + 4) ^ lr) << 4));
        ldm4(bh[0], bL + ((gB ^ lr) << 4));
        ldm4(bh[1], bL + 2048 + ((gB ^ lr) << 4));
        ldm4(bl[0], bL + (((gB + 4) ^ lr) << 4));
        ldm4(bl[1], bL + 2048 + (((gB + 4) ^ lr) << 4));
#pragma unroll
        for (int it = 0; it < 2; ++it)
#pragma unroll
            for (int jt = 0; jt < 4; ++jt)
                mma16(acc[it][jt], ah[it], &bh[jt >> 1][(jt & 1) * 2]);
#pragma unroll
        for (int it = 0; it < 2; ++it)
#pragma unroll
            for (int jt = 0; jt < 4; ++jt)
                mma16(acc[it][jt], ah[it], &bl[jt >> 1][(jt & 1) * 2]);
#pragma unroll
        for (int it = 0; it < 2; ++it)
#pragma unroll
            for (int jt = 0; jt < 4; ++jt)
                mma16(acc[it][jt], al[it], &bh[jt >> 1][(jt & 1) * 2]);
    }
}

// double-buffered, one sync per chunk (round-4 ordering), register prefetch of f32
__device__ __forceinline__ void run_loop64f(char* smc, uint32_t smem_u,
                                            const float* gA, const float* gB,
                                            int nch, float acc[2][4][4],
                                            int wm, int wn, int lane, int tid) {
    int rr = tid >> 1, half = tid & 1;
    const float* pA = gA + (size_t)rr * NN + half * 16;
    const float* pB = gB + (size_t)rr * NN + half * 16;
    float4 va[4], vb[4];
#pragma unroll
    for (int c = 0; c < 4; ++c) {
        va[c] = *(const float4*)(pA + c * 4);
        vb[c] = *(const float4*)(pB + c * 4);
    }
    for (int s = 0; s < nch; ++s) {
        char* buf = smc + (s & 1) * STG64;
        cvt_store16(buf, rr, half, va);
        cvt_store16(buf + 8192, rr, half, vb);
        if (s + 1 < nch) {
            int o = (s + 1) * CHK;
#pragma unroll
            for (int c = 0; c < 4; ++c) {
                va[c] = *(const float4*)(pA + o + c * 4);
                vb[c] = *(const float4*)(pB + o + c * 4);
            }
        }
        __syncthreads();
        compute_chunk64(smem_u + (s & 1) * STG64, acc, wm, wn, lane);
    }
    __syncthreads();
}

// ================= 64x32 path (NS GEMMs, pipelined cp.async; unchanged) =================
__device__ __forceinline__ void issue_chunk32(uint32_t dstBase,
                                              const __half* Ph, const __half* Pl,
                                              const __half* Qh, const __half* Ql,
                                              int k0, int tid) {
#pragma unroll
    for (int i = 0; i < 6; ++i) {
        int n = i * 128 + tid;          // 0..767
        bool isB = n >= 512;
        int m = isB ? n - 512 : n;
        int row = m >> 3, g = m & 7;
        const __half* hbase = isB ? (g < 4 ? Qh : Ql) : (g < 4 ? Ph : Pl);
        const __half* src = hbase + (size_t)row * CC + k0 + 8 * (g & 3);
        uint32_t dst = dstBase + (isB ? 8192 : 0) + row * 128 + ((g ^ (row & 7)) << 4);
        CP16(dst, src);
    }
}

__device__ __forceinline__ void compute_chunk32(uint32_t stBase, float acc[2][2][4],
                                                int wm, int wn, int lane) {
    int lr = lane & 7;
    int lt8 = (lane >> 3) & 1;
    int lkh = (lane >> 4) & 1;
    uint32_t aL = stBase + (wm * 32 + lt8 * 8 + lr) * 128;
    uint32_t bL = stBase + 8192 + (wn * 16 + lkh * 8 + lr) * 128;
#pragma unroll
    for (int ks = 0; ks < 2; ++ks) {
        unsigned ah[2][4], al[2][4], bh[4], bl[4];
        int gA = ks * 2 + lkh, gB = ks * 2 + lt8;
        ldm4(ah[0], aL + ((gA ^ lr) << 4));
        ldm4(ah[1], aL + 2048 + ((gA ^ lr) << 4));
        ldm4(al[0], aL + (((gA + 4) ^ lr) << 4));
        ldm4(al[1], aL + 2048 + (((gA + 4) ^ lr) << 4));
        ldm4(bh, bL + ((gB ^ lr) << 4));
        ldm4(bl, bL + (((gB + 4) ^ lr) << 4));
#pragma unroll
        for (int it = 0; it < 2; ++it)
#pragma unroll
            for (int jt = 0; jt < 2; ++jt)
                mma16(acc[it][jt], ah[it], &bh[jt * 2]);
#pragma unroll
        for (int it = 0; it < 2; ++it)
#pragma unroll
            for (int jt = 0; jt < 2; ++jt)
                mma16(acc[it][jt], ah[it], &bl[jt * 2]);
#pragma unroll
        for (int it = 0; it < 2; ++it)
#pragma unroll
            for (int jt = 0; jt < 2; ++jt)
                mma16(acc[it][jt], al[it], &bh[jt * 2]);
    }
}

__device__ __forceinline__ void run_loop32(uint32_t smem_u,
                                           const __half* Ph, const __half* Pl,
                                           const __half* Qh, const __half* Ql,
                                           float acc[2][2][4],
                                           int wm, int wn, int lane, int tid) {
    const int nch = CC / CHK;   // 8
    issue_chunk32(smem_u, Ph, Pl, Qh, Ql, 0, tid);
    CP_COMMIT();
    issue_chunk32(smem_u + STG32, Ph, Pl, Qh, Ql, CHK, tid);
    CP_COMMIT();
    int st = 0;
#pragma unroll
    for (int s = 0; s < nch; ++s) {
        CP_WAIT1();
        __syncthreads();
        if (s + 2 < nch) {
            int st2 = st + 2;
            if (st2 >= 3) st2 -= 3;
            issue_chunk32(smem_u + st2 * STG32, Ph, Pl, Qh, Ql, (s + 2) * CHK, tid);
        }
        CP_COMMIT();
        compute_chunk32(smem_u + st * STG32, acc, wm, wn, lane);
        if (++st == 3) st = 0;
    }
}

// ---------------- rowsum/sumsq + trace ----------------
__global__ __launch_bounds__(256) void rowsumq_kernel(const float* __restrict__ X,
                                                      float* __restrict__ s,
                                                      float* __restrict__ q) {
    int c = blockIdx.x, b = blockIdx.y;
    const float4* row = (const float4*)(X + ((size_t)b * CC + c) * NN);
    float acc = 0.f, accq = 0.f;
    for (int i = threadIdx.x; i < NN / 4; i += 256) {
        float4 v = row[i];
        acc += v.x + v.y + v.z + v.w;
        accq += v.x * v.x + v.y * v.y + v.z * v.z + v.w * v.w;
    }
    __shared__ float ss[256], sq[256];
    ss[threadIdx.x] = acc;
    sq[threadIdx.x] = accq;
    __syncthreads();
    for (int st = 128; st > 0; st >>= 1) {
        if (threadIdx.x < st) {
            ss[threadIdx.x] += ss[threadIdx.x + st];
            sq[threadIdx.x] += sq[threadIdx.x + st];
        }
        __syncthreads();
    }
    if (threadIdx.x == 0) {
        s[b * CC + c] = ss[0];
        q[b * CC + c] = sq[0];
    }
}

__global__ __launch_bounds__(256) void trred_kernel(const float* __restrict__ s,
                                                    const float* __restrict__ q,
                                                    float* __restrict__ tr) {
    int b = blockIdx.x, c = threadIdx.x;
    const float inv_n = 1.0f / (float)NN;
    const float inv_n2 = inv_n * inv_n;
    float sv = s[b * CC + c];
    float v = q[b * CC + c] * inv_n - sv * sv * inv_n2;
    __shared__ float sm[256];
    sm[c] = v;
    __syncthreads();
    for (int st = 128; st > 0; st >>= 1) {
        if (c < st) sm[c] += sm[c + st];
        __syncthreads();
    }
    if (c == 0) tr[b] = sm[0];
}

// ---------------- gram: reads f32 X directly, splits on the fly ----------------
__global__ __launch_bounds__(128, 4) void gram_mma(const float* __restrict__ X,
                                                   const float* __restrict__ sv,
                                                   const float* __restrict__ trv,
                                                   __half* __restrict__ H,
                                                   __half* __restrict__ L) {
    extern __shared__ unsigned swm[];
    char* smc = (char*)swm;
    uint32_t smem_u = smem_u32(swm);
    int b = blockIdx.z, tile = blockIdx.x;
    int i0 = c_TI[tile] * 64, j0 = c_TJ[tile] * 64;
    bool mirror = (i0 != j0);
    int tid = threadIdx.x;
    int warp = tid >> 5, lane = tid & 31;
    int wm = warp >> 1, wn = warp & 1, g = lane >> 2, t = lane & 3;
    float acc[2][4][4] = {};

    const float* Xb = X + (size_t)b * CC * NN;
    run_loop64f(smc, smem_u, Xb + (size_t)i0 * NN, Xb + (size_t)j0 * NN, NN / CHK,
                acc, wm, wn, lane, tid);

    __half* M = (__half*)swm;        // transpose buffer [mat*2+comp][64][MP]

    const float inv_n = 1.0f / (float)NN;
    const float inv_n2 = inv_n * inv_n;
    float invtr = 1.0f / trv[b];
    float c1 = INVS2 * inv_n * invtr;
    float c2 = inv_n2 * invtr;
    __half* Ah = H + (size_t)b * CC * CC;
    __half* Al = L + (size_t)b * CC * CC;
    __half* B0h = H + (size_t)MATSZ + (size_t)b * CC * CC;
    __half* B0l = L + (size_t)MATSZ + (size_t)b * CC * CC;
#pragma unroll
    for (int it = 0; it < 2; ++it)
#pragma unroll
        for (int jt = 0; jt < 4; ++jt) {
            int gi = i0 + wm * 32 + it * 16 + g;
            int gj = j0 + wn * 32 + jt * 8 + 2 * t;
            float* ca = acc[it][jt];
#pragma unroll
            for (int h = 0; h < 2; ++h) {
                int r = gi + h * 8;
                float si = sv[b * CC + r];
                float a0 = ca[h * 2 + 0] * c1 - si * sv[b * CC + gj] * c2;
                float a1 = ca[h * 2 + 1] * c1 - si * sv[b * CC + gj + 1] * c2;
                float w0 = (r == gj ? 1.5f : 0.0f) - 0.5f * a0;
                float w1 = (r == gj + 1 ? 1.5f : 0.0f) - 0.5f * a1;
                unsigned hiA, loA, hiB, loB;
                split_pair(a0, a1, hiA, loA);
                *(unsigned*)&Ah[(size_t)r * CC + gj] = hiA;
                *(unsigned*)&Al[(size_t)r * CC + gj] = loA;
                split_pair(w0, w1, hiB, loB);
                *(unsigned*)&B0h[(size_t)r * CC + gj] = hiB;
                *(unsigned*)&B0l[(size_t)r * CC + gj] = loB;
                if (mirror) {
                    int r_l = r - i0, c_l = gj - j0;
                    __half2 x;
                    x = *(__half2*)&hiA;
                    M[(0 * 64 + c_l) * MP + r_l] = __low2half(x);
                    M[(0 * 64 + c_l + 1) * MP + r_l] = __high2half(x);
                    x = *(__half2*)&loA;
                    M[(1 * 64 + c_l) * MP + r_l] = __low2half(x);
                    M[(1 * 64 + c_l + 1) * MP + r_l] = __high2half(x);
                    x = *(__half2*)&hiB;
                    M[(2 * 64 + c_l) * MP + r_l] = __low2half(x);
                    M[(2 * 64 + c_l + 1) * MP + r_l] = __high2half(x);
                    x = *(__half2*)&loB;
                    M[(3 * 64 + c_l) * MP + r_l] = __low2half(x);
                    M[(3 * 64 + c_l + 1) * MP + r_l] = __high2half(x);
                }
            }
        }
    if (mirror) {
        __syncthreads();
#pragma unroll
        for (int u = 0; u < 2; ++u) {
            int unit = tid + u * 128;        // 0..255
            int mc = unit >> 6;              // 0:Ah 1:Al 2:B0h 3:B0l
            int c_l = unit & 63;
            const uint4* srcv = (const uint4*)(M + (mc * 64 + c_l) * MP);
            __half* dstp = (mc == 0) ? Ah : (mc == 1) ? Al : (mc == 2) ? B0h : B0l;
            uint4* dstv = (uint4*)(dstp + (size_t)(j0 + c_l) * CC + i0);
#pragma unroll
            for (int w2 = 0; w2 < 8; ++w2) dstv[w2] = srcv[w2];
        }
    }
}

// ---------------- NS GEMM (64x32 tiles, slot-indexed, optional pair via grid.y) ----------------
// EPI 0: C=P@Q     EPI 1: C=1.5I-0.5(P@Q)     EPI 2: triuvec(P@Q * sqrt(tr))
template <int EPI>
__global__ __launch_bounds__(128, 5) void ns_mma(__half* __restrict__ H,
                                                 __half* __restrict__ L,
                                                 int p0, int q0, int cs0,
                                                 int p1, int q1, int cs1,
                                                 const float* __restrict__ trv,
                                                 float* __restrict__ outg) {
    extern __shared__ unsigned swm[];
    uint32_t smem_u = smem_u32(swm);
    int b = blockIdx.z, tile = blockIdx.x;
    int sel = blockIdx.y;
    int ps = sel ? p1 : p0, qs = sel ? q1 : q0, cs = sel ? cs1 : cs0;
    int i0 = c_SI[tile] * 64, j0 = c_SJ[tile] * 32;
    int tid = threadIdx.x;
    int warp = tid >> 5, lane = tid & 31;
    int wm = warp >> 1, wn = warp & 1, g = lane >> 2, t = lane & 3;
    float acc[2][2][4] = {};

    size_t mb = (size_t)b * CC * CC;
    const __half* Ph = H + (size_t)ps * MATSZ + mb + (size_t)i0 * CC;
    const __half* Pl = L + (size_t)ps * MATSZ + mb + (size_t)i0 * CC;
    const __half* Qh = H + (size_t)qs * MATSZ + mb + (size_t)j0 * CC;
    const __half* Ql = L + (size_t)qs * MATSZ + mb + (size_t)j0 * CC;
    run_loop32(smem_u, Ph, Pl, Qh, Ql, acc, wm, wn, lane, tid);

    __half* Ch = H + (size_t)cs * MATSZ + mb;
    __half* Cl = L + (size_t)cs * MATSZ + mb;

    if (EPI == 2) {
        float scale = sqrtf(trv[b]) * INVS2;
#pragma unroll
        for (int it = 0; it < 2; ++it)
#pragma unroll
            for (int jt = 0; jt < 2; ++jt) {
                int gi = i0 + wm * 32 + it * 16 + g;
                int gj = j0 + wn * 16 + jt * 8 + 2 * t;
                float* ca = acc[it][jt];
#pragma unroll
                for (int h = 0; h < 2; ++h) {
                    int r = gi + h * 8;
                    float v0 = ca[h * 2 + 0] * scale, v1 = ca[h * 2 + 1] * scale;
                    int base = r * CC - (r * (r - 1)) / 2 - r;
                    if (gj >= r) outg[(size_t)b * OUTC + base + gj] = v0;
                    if (gj + 1 >= r) outg[(size_t)b * OUTC + base + gj + 1] = v1;
                }
            }
    } else {
        __syncthreads();             // stage smem reusable as transpose buffer
        __half* M = (__half*)swm;    // [comp(2)][32][MP]
#pragma unroll
        for (int it = 0; it < 2; ++it)
#pragma unroll
            for (int jt = 0; jt < 2; ++jt) {
                int gi = i0 + wm * 32 + it * 16 + g;
                int gj = j0 + wn * 16 + jt * 8 + 2 * t;
                float* ca = acc[it][jt];
#pragma unroll
                for (int h = 0; h < 2; ++h) {
                    int r = gi + h * 8;
                    float v0 = ca[h * 2 + 0] * INVS2, v1 = ca[h * 2 + 1] * INVS2;
                    if (EPI == 1) {
                        v0 = (r == gj ? 1.5f : 0.0f) - 0.5f * v0;
                        v1 = (r == gj + 1 ? 1.5f : 0.0f) - 0.5f * v1;
                    }
                    unsigned hi, lo;
                    split_pair(v0, v1, hi, lo);
                    *(unsigned*)&Ch[(size_t)r * CC + gj] = hi;
                    *(unsigned*)&Cl[(size_t)r * CC + gj] = lo;
                    int r_l = r - i0, c_l = gj - j0;
                    __half2 x = *(__half2*)&hi;
                    M[c_l * MP + r_l] = __low2half(x);
                    M[(c_l + 1) * MP + r_l] = __high2half(x);
                    x = *(__half2*)&lo;
                    M[(32 + c_l) * MP + r_l] = __low2half(x);
                    M[(32 + c_l + 1) * MP + r_l] = __high2half(x);
                }
            }
        __syncthreads();
        int unit = tid >> 1;             // 0..63
        int comp = unit >> 5, c_l = unit & 31;
        int seg = (tid & 1) * 32;        // halves
        const uint4* srcv = (const uint4*)(M + (comp * 32 + c_l) * MP + seg);
        __half* dstp = (comp ? Cl : Ch) + (size_t)(j0 + c_l) * CC + i0 + seg;
        uint4* dstv = (uint4*)dstp;
        dstv[0] = srcv[0];
        dstv[1] = srcv[1];
        dstv[2] = srcv[2];
        dstv[3] = srcv[3];
    }
}

// ---------------- launch ----------------
extern "C" void kernel_launch(void* const* d_in, const int* in_sizes, int n_in,
                              void* d_out, int out_size) {
    const float* x = (const float*)d_in[0];
    float* out = (float*)d_out;

    __half *H, *L;
    float *s, *q, *tr;
    cudaGetSymbolAddress((void**)&H, g_H);
    cudaGetSymbolAddress((void**)&L, g_L);
    cudaGetSymbolAddress((void**)&s, g_s);
    cudaGetSymbolAddress((void**)&q, g_q);
    cudaGetSymbolAddress((void**)&tr, g_tr);

    cudaFuncSetAttribute(gram_mma, cudaFuncAttributeMaxDynamicSharedMemorySize, SMEM64);
    cudaFuncSetAttribute(ns_mma<0>, cudaFuncAttributeMaxDynamicSharedMemorySize, SMEM32);
    cudaFuncSetAttribute(ns_mma<1>, cudaFuncAttributeMaxDynamicSharedMemorySize, SMEM32);
    cudaFuncSetAttribute(ns_mma<2>, cudaFuncAttributeMaxDynamicSharedMemorySize, SMEM32);

    rowsumq_kernel<<<dim3(CC, BB), 256>>>(x, s, q);
    trred_kernel<<<BB, 256>>>(s, q, tr);

    gram_mma<<<dim3(10, 1, BB), 128, SMEM64>>>(x, s, tr, H, L);

    dim3 g1(20, 1, BB), g2(20, 2, BB);
    // slots: A=0 B0=1 B1=2 Y0=3 Y1=4 Z0=5 Z1=6
    ns_mma<0><<<g1, 128, SMEM32>>>(H, L, 0, 1, 3, 0, 1, 3, tr, out);  // Y0 = A@B0
    // iter 1
    ns_mma<1><<<g1, 128, SMEM32>>>(H, L, 1, 3, 2, 1, 3, 2, tr, out);  // B1 = f(B0@Y0)
    ns_mma<0><<<g2, 128, SMEM32>>>(H, L, 3, 2, 4, 2, 1, 5, tr, out);  // Y1=Y0@B1 || Z0=B1@B0
    // iter 2
    ns_mma<1><<<g1, 128, SMEM32>>>(H, L, 5, 4, 1, 5, 4, 1, tr, out);  // B0 = f(Z0@Y1)
    ns_mma<0><<<g2, 128, SMEM32>>>(H, L, 4, 1, 3, 1, 5, 6, tr, out);  // Y0=Y1@B0 || Z1=B0@Z0
    // iter 3
    ns_mma<1><<<g1, 128, SMEM32>>>(H, L, 6, 3, 2, 6, 3, 2, tr, out);  // B1 = f(Z1@Y0)
    ns_mma<0><<<g2, 128, SMEM32>>>(H, L, 3, 2, 4, 2, 6, 5, tr, out);  // Y1=Y0@B1 || Z0=B1@Z1
    // iter 4 (Z update dead -> dropped)
    ns_mma<1><<<g1, 128, SMEM32>>>(H, L, 5, 4, 1, 5, 4, 1, tr, out);  // B0 = f(Z0@Y1)
    ns_mma<2><<<g1, 128, SMEM32>>>(H, L, 4, 1, 0, 4, 1, 0, tr, out);  // triuvec(Y1@B0)
}

// round 14
// speedup vs baseline: 1.2021x; 1.2021x over previous
#include <cuda_runtime.h>
#include <cuda_fp16.h>
#include <math.h>
#include <stdint.h>

#define BB 32
#define CC 256
#define NN 3136
#define OUTC 32896            // 256*257/2
#define MATSZ (BB*CC*CC)
#define XSZ (BB*CC*NN)

#define CHK 32
#define STG64 16384           // gram stage: A(8K)+B(8K)
#define SMEM64 (3*STG64)      // 49152
#define STG32 12288           // ns stage: A(8K)+B(4K)
#define SMEM32 (3*STG32)      // 36864
#define SSCALE 64.0f
#define INVS2 (1.0f/(SSCALE*SSCALE))
#define MP 72                 // transpose-buffer pitch in halves
#define NCT 640               // fused ns grid size (all resident: 5/SM * 148 = 740)

// gram: 10 upper 64x64 tiles
__device__ __constant__ int c_TI[10] = {0,0,0,0,1,1,1,2,2,3};
__device__ __constant__ int c_TJ[10] = {0,1,2,3,1,2,3,2,3,3};
// ns: 20 tiles 64x32 with j*32 >= i*64
__device__ __constant__ int c_SI[20] = {0,0,0,0,0,0,0,0, 1,1,1,1,1,1, 2,2,2,2, 3,3};
__device__ __constant__ int c_SJ[20] = {0,1,2,3,4,5,6,7, 2,3,4,5,6,7, 4,5,6,7, 6,7};

// NS schedule: 9 steps; per step up to 2 independent jobs {p,q,cs,epi}
__device__ __constant__ int c_nj[9]          = {1,1,2,1,2,1,2,1,1};
__device__ __constant__ int c_job[9][2][4] = {
    {{0,1,3,0},{0,0,0,0}},   // Y0 = A@B0
    {{1,3,2,1},{0,0,0,0}},   // B1 = f(B0@Y0)
    {{3,2,4,0},{2,1,5,0}},   // Y1=Y0@B1 | Z0=B1@B0
    {{5,4,1,1},{0,0,0,0}},   // B0 = f(Z0@Y1)
    {{4,1,3,0},{1,5,6,0}},   // Y0=Y1@B0 | Z1=B0@Z0
    {{6,3,2,1},{0,0,0,0}},   // B1 = f(Z1@Y0)
    {{3,2,4,0},{2,6,5,0}},   // Y1=Y0@B1 | Z0=B1@Z1
    {{5,4,1,1},{0,0,0,0}},   // B0 = f(Z0@Y1)
    {{4,1,0,2},{0,0,0,0}},   // triuvec(Y1@B0)
};

// ---------------- scratch: matrices stored as hi/lo fp16 pairs ----------------
// slots: A=0 B0=1 B1=2 Y0=3 Y1=4 Z0=5 Z1=6
__device__ __align__(16) __half g_H[7*MATSZ];
__device__ __align__(16) __half g_L[7*MATSZ];
__device__ __align__(16) __half g_Xh[XSZ];
__device__ __align__(16) __half g_Xl[XSZ];
__device__ float g_s[BB*CC];
__device__ float g_q[BB*CC];
__device__ float g_tr[BB];
__device__ unsigned g_barc;   // barrier arrival counter (self-resets to 0)
__device__ unsigned g_barg;   // barrier generation (monotonic)

// ---------------- primitives ----------------
__device__ __forceinline__ uint32_t smem_u32(const void* p) {
    uint32_t a;
    asm("{ .reg .u64 t; cvta.to.shared.u64 t, %1; cvt.u32.u64 %0, t; }" : "=r"(a) : "l"(p));
    return a;
}

__device__ __forceinline__ void mma16(float* c, const unsigned* a, const unsigned* b) {
    asm volatile(
        "mma.sync.aligned.m16n8k16.row.col.f32.f16.f16.f32 "
        "{%0,%1,%2,%3}, {%4,%5,%6,%7}, {%8,%9}, {%0,%1,%2,%3};"
        : "+f"(c[0]), "+f"(c[1]), "+f"(c[2]), "+f"(c[3])
        : "r"(a[0]), "r"(a[1]), "r"(a[2]), "r"(a[3]), "r"(b[0]), "r"(b[1]));
}

__device__ __forceinline__ void ldm4(unsigned r[4], uint32_t a) {
    asm volatile("ldmatrix.sync.aligned.m8n8.x4.shared.b16 {%0,%1,%2,%3}, [%4];"
                 : "=r"(r[0]), "=r"(r[1]), "=r"(r[2]), "=r"(r[3]) : "r"(a));
}

#define CP16(dst, src) \
    asm volatile("cp.async.cg.shared.global [%0], [%1], 16;" :: "r"(dst), "l"(src))
#define CP_COMMIT() asm volatile("cp.async.commit_group;" ::: "memory")
#define CP_WAIT1() asm volatile("cp.async.wait_group 1;" ::: "memory")

__device__ __forceinline__ void split_pair(float v0, float v1, unsigned& hi, unsigned& lo) {
    float s0 = v0 * SSCALE, s1 = v1 * SSCALE;
    __half h0 = __float2half_rn(s0), h1 = __float2half_rn(s1);
    __half l0 = __float2half_rn(s0 - __half2float(h0));
    __half l1 = __float2half_rn(s1 - __half2float(h1));
    __half2 hh = __halves2half2(h0, h1), ll = __halves2half2(l0, l1);
    hi = *(unsigned*)&hh;
    lo = *(unsigned*)&ll;
}

// grid-wide barrier: sense-reversing; safe because all NCT CTAs are co-resident.
__device__ __forceinline__ void grid_barrier() {
    __syncthreads();
    if (threadIdx.x == 0) {
        __threadfence();
        unsigned gen = *(volatile unsigned*)&g_barg;
        unsigned t = atomicAdd(&g_barc, 1u);
        if (t == NCT - 1u) {
            g_barc = 0;
            __threadfence();
            *(volatile unsigned*)&g_barg = gen + 1u;
        } else {
            while (*(volatile unsigned*)&g_barg == gen) __nanosleep(64);
        }
        __threadfence();
    }
    __syncthreads();
}

// ================= 64x64 path (gram, pipelined) =================
__device__ __forceinline__ void issue_chunk64(uint32_t dstBase,
                                              const __half* Ah, const __half* Al,
                                              const __half* Bh, const __half* Bl,
                                              int strideH, int k0, int tid) {
#pragma unroll
    for (int i = 0; i < 8; ++i) {
        int n = i * 128 + tid;
        int mat = n >> 9;
        int m = n & 511;
        int row = m >> 3, g = m & 7;
        const __half* hbase = (mat == 0) ? (g < 4 ? Ah : Al) : (g < 4 ? Bh : Bl);
        const __half* src = hbase + (size_t)row * strideH + k0 + 8 * (g & 3);
        uint32_t dst = dstBase + mat * 8192 + row * 128 + ((g ^ (row & 7)) << 4);
        CP16(dst, src);
    }
}

__device__ __forceinline__ void compute_chunk64(uint32_t stBase, float acc[2][4][4],
                                                int wm, int wn, int lane) {
    int lr = lane & 7;
    int lt8 = (lane >> 3) & 1;
    int lkh = (lane >> 4) & 1;
    uint32_t aL = stBase + (wm * 32 + lt8 * 8 + lr) * 128;
    uint32_t bL = stBase + 8192 + (wn * 32 + lkh * 8 + lr) * 128;
#pragma unroll
    for (int ks = 0; ks < 2; ++ks) {
        unsigned ah[2][4], al[2][4], bh[2][4], bl[2][4];
        int gA = ks * 2 + lkh, gB = ks * 2 + lt8;
        ldm4(ah[0], aL + ((gA ^ lr) << 4));
        ldm4(ah[1], aL + 2048 + ((gA ^ lr) << 4));
        ldm4(al[0], aL + (((gA + 4) ^ lr) << 4));
        ldm4(al[1], aL + 2048 + (((gA + 4) ^ lr) << 4));
        ldm4(bh[0], bL + ((gB ^ lr) << 4));
        ldm4(bh[1], bL + 2048 + ((gB ^ lr) << 4));
        ldm4(bl[0], bL + (((gB + 4) ^ lr) << 4));
        ldm4(bl[1], bL + 2048 + (((gB + 4) ^ lr) << 4));
#pragma unroll
        for (int it = 0; it < 2; ++it)
#pragma unroll
            for (int jt = 0; jt < 4; ++jt)
                mma16(acc[it][jt], ah[it], &bh[jt >> 1][(jt & 1) * 2]);
#pragma unroll
        for (int it = 0; it < 2; ++it)
#pragma unroll
            for (int jt = 0; jt < 4; ++jt)
                mma16(acc[it][jt], ah[it], &bl[jt >> 1][(jt & 1) * 2]);
#pragma unroll
        for (int it = 0; it < 2; ++it)
#pragma unroll
            for (int jt = 0; jt < 4; ++jt)
                mma16(acc[it][jt], al[it], &bh[jt >> 1][(jt & 1) * 2]);
    }
}

__device__ __forceinline__ void run_loop64(uint32_t smem_u,
                                           const __half* Ah, const __half* Al,
                                           const __half* Bh, const __half* Bl,
                                           int strideH, int nch, float acc[2][4][4],
                                           int wm, int wn, int lane, int tid) {
    issue_chunk64(smem_u, Ah, Al, Bh, Bl, strideH, 0, tid);
    CP_COMMIT();
    issue_chunk64(smem_u + STG64, Ah, Al, Bh, Bl, strideH, CHK, tid);
    CP_COMMIT();
    int st = 0;
    for (int s = 0; s < nch; ++s) {
        CP_WAIT1();
        __syncthreads();
        if (s + 2 < nch) {
            int st2 = st + 2;
            if (st2 >= 3) st2 -= 3;
            issue_chunk64(smem_u + st2 * STG64, Ah, Al, Bh, Bl, strideH, (s + 2) * CHK, tid);
        }
        CP_COMMIT();
        compute_chunk64(smem_u + st * STG64, acc, wm, wn, lane);
        if (++st == 3) st = 0;
    }
}

// ================= 64x32 path (NS GEMMs, pipelined) =================
__device__ __forceinline__ void issue_chunk32(uint32_t dstBase,
                                              const __half* Ph, const __half* Pl,
                                              const __half* Qh, const __half* Ql,
                                              int k0, int tid) {
#pragma unroll
    for (int i = 0; i < 6; ++i) {
        int n = i * 128 + tid;          // 0..767
        bool isB = n >= 512;
        int m = isB ? n - 512 : n;
        int row = m >> 3, g = m & 7;
        const __half* hbase = isB ? (g < 4 ? Qh : Ql) : (g < 4 ? Ph : Pl);
        const __half* src = hbase + (size_t)row * CC + k0 + 8 * (g & 3);
        uint32_t dst = dstBase + (isB ? 8192 : 0) + row * 128 + ((g ^ (row & 7)) << 4);
        CP16(dst, src);
    }
}

__device__ __forceinline__ void compute_chunk32(uint32_t stBase, float acc[2][2][4],
                                                int wm, int wn, int lane) {
    int lr = lane & 7;
    int lt8 = (lane >> 3) & 1;
    int lkh = (lane >> 4) & 1;
    uint32_t aL = stBase + (wm * 32 + lt8 * 8 + lr) * 128;
    uint32_t bL = stBase + 8192 + (wn * 16 + lkh * 8 + lr) * 128;
#pragma unroll
    for (int ks = 0; ks < 2; ++ks) {
        unsigned ah[2][4], al[2][4], bh[4], bl[4];
        int gA = ks * 2 + lkh, gB = ks * 2 + lt8;
        ldm4(ah[0], aL + ((gA ^ lr) << 4));
        ldm4(ah[1], aL + 2048 + ((gA ^ lr) << 4));
        ldm4(al[0], aL + (((gA + 4) ^ lr) << 4));
        ldm4(al[1], aL + 2048 + (((gA + 4) ^ lr) << 4));
        ldm4(bh, bL + ((gB ^ lr) << 4));
        ldm4(bl, bL + (((gB + 4) ^ lr) << 4));
#pragma unroll
        for (int it = 0; it < 2; ++it)
#pragma unroll
            for (int jt = 0; jt < 2; ++jt)
                mma16(acc[it][jt], ah[it], &bh[jt * 2]);
#pragma unroll
        for (int it = 0; it < 2; ++it)
#pragma unroll
            for (int jt = 0; jt < 2; ++jt)
                mma16(acc[it][jt], ah[it], &bl[jt * 2]);
#pragma unroll
        for (int it = 0; it < 2; ++it)
#pragma unroll
            for (int jt = 0; jt < 2; ++jt)
                mma16(acc[it][jt], al[it], &bh[jt * 2]);
    }
}

__device__ __forceinline__ void run_loop32(uint32_t smem_u,
                                           const __half* Ph, const __half* Pl,
                                           const __half* Qh, const __half* Ql,
                                           float acc[2][2][4],
                                           int wm, int wn, int lane, int tid) {
    const int nch = CC / CHK;   // 8
    issue_chunk32(smem_u, Ph, Pl, Qh, Ql, 0, tid);
    CP_COMMIT();
    issue_chunk32(smem_u + STG32, Ph, Pl, Qh, Ql, CHK, tid);
    CP_COMMIT();
    int st = 0;
#pragma unroll
    for (int s = 0; s < nch; ++s) {
        CP_WAIT1();
        __syncthreads();
        if (s + 2 < nch) {
            int st2 = st + 2;
            if (st2 >= 3) st2 -= 3;
            issue_chunk32(smem_u + st2 * STG32, Ph, Pl, Qh, Ql, (s + 2) * CHK, tid);
        }
        CP_COMMIT();
        compute_chunk32(smem_u + st * STG32, acc, wm, wn, lane);
        if (++st == 3) st = 0;
    }
}

// one NS GEMM job: tile (64x32), batch b, slots p,q -> cs with epilogue epi
__device__ void ns_job(__half* H, __half* L, int ps, int qs, int cs, int epi,
                       int tile, int b, const float* trv, float* outg,
                       unsigned* swm, uint32_t smem_u) {
    int i0 = c_SI[tile] * 64, j0 = c_SJ[tile] * 32;
    int tid = threadIdx.x;
    int warp = tid >> 5, lane = tid & 31;
    int wm = warp >> 1, wn = warp & 1, g = lane >> 2, t = lane & 3;
    float acc[2][2][4] = {};

    size_t mb = (size_t)b * CC * CC;
    const __half* Ph = H + (size_t)ps * MATSZ + mb + (size_t)i0 * CC;
    const __half* Pl = L + (size_t)ps * MATSZ + mb + (size_t)i0 * CC;
    const __half* Qh = H + (size_t)qs * MATSZ + mb + (size_t)j0 * CC;
    const __half* Ql = L + (size_t)qs * MATSZ + mb + (size_t)j0 * CC;
    run_loop32(smem_u, Ph, Pl, Qh, Ql, acc, wm, wn, lane, tid);

    __half* Ch = H + (size_t)cs * MATSZ + mb;
    __half* Cl = L + (size_t)cs * MATSZ + mb;

    if (epi == 2) {
        float scale = sqrtf(trv[b]) * INVS2;
#pragma unroll
        for (int it = 0; it < 2; ++it)
#pragma unroll
            for (int jt = 0; jt < 2; ++jt) {
                int gi = i0 + wm * 32 + it * 16 + g;
                int gj = j0 + wn * 16 + jt * 8 + 2 * t;
                float* ca = acc[it][jt];
#pragma unroll
                for (int h = 0; h < 2; ++h) {
                    int r = gi + h * 8;
                    float v0 = ca[h * 2 + 0] * scale, v1 = ca[h * 2 + 1] * scale;
                    int base = r * CC - (r * (r - 1)) / 2 - r;
                    if (gj >= r) outg[(size_t)b * OUTC + base + gj] = v0;
                    if (gj + 1 >= r) outg[(size_t)b * OUTC + base + gj + 1] = v1;
                }
            }
    } else {
        __syncthreads();             // stage smem reusable as transpose buffer
        __half* M = (__half*)swm;    // [comp(2)][32][MP]
#pragma unroll
        for (int it = 0; it < 2; ++it)
#pragma unroll
            for (int jt = 0; jt < 2; ++jt) {
                int gi = i0 + wm * 32 + it * 16 + g;
                int gj = j0 + wn * 16 + jt * 8 + 2 * t;
                float* ca = acc[it][jt];
#pragma unroll
                for (int h = 0; h < 2; ++h) {
                    int r = gi + h * 8;
                    float v0 = ca[h * 2 + 0] * INVS2, v1 = ca[h * 2 + 1] * INVS2;
                    if (epi == 1) {
                        v0 = (r == gj ? 1.5f : 0.0f) - 0.5f * v0;
                        v1 = (r == gj + 1 ? 1.5f : 0.0f) - 0.5f * v1;
                    }
                    unsigned hi, lo;
                    split_pair(v0, v1, hi, lo);
                    *(unsigned*)&Ch[(size_t)r * CC + gj] = hi;
                    *(unsigned*)&Cl[(size_t)r * CC + gj] = lo;
                    int r_l = r - i0, c_l = gj - j0;
                    __half2 x = *(__half2*)&hi;
                    M[c_l * MP + r_l] = __low2half(x);
                    M[(c_l + 1) * MP + r_l] = __high2half(x);
                    x = *(__half2*)&lo;
                    M[(32 + c_l) * MP + r_l] = __low2half(x);
                    M[(32 + c_l + 1) * MP + r_l] = __high2half(x);
                }
            }
        __syncthreads();
        int unit = tid >> 1;             // 0..63
        int comp = unit >> 5, c_l = unit & 31;
        int seg = (tid & 1) * 32;        // halves
        const uint4* srcv = (const uint4*)(M + (comp * 32 + c_l) * MP + seg);
        __half* dstp = (comp ? Cl : Ch) + (size_t)(j0 + c_l) * CC + i0 + seg;
        uint4* dstv = (uint4*)dstp;
        dstv[0] = srcv[0];
        dstv[1] = srcv[1];
        dstv[2] = srcv[2];
        dstv[3] = srcv[3];
    }
}

// ---------------- fused persistent NS chain ----------------
__global__ __launch_bounds__(128, 5) void ns_fused(__half* __restrict__ H,
                                                   __half* __restrict__ L,
                                                   const float* __restrict__ trv,
                                                   float* __restrict__ outg) {
    extern __shared__ unsigned swm[];
    uint32_t smem_u = smem_u32(swm);
    int tile = blockIdx.x;       // 0..19
    int b = blockIdx.z;          // 0..31
    for (int s = 0; s < 9; ++s) {
        int nj = c_nj[s];
        for (int j = 0; j < nj; ++j) {
            ns_job(H, L, c_job[s][j][0], c_job[s][j][1], c_job[s][j][2], c_job[s][j][3],
                   tile, b, trv, outg, swm, smem_u);
            __syncthreads();     // smem safe before next job's cp.async
        }
        if (s < 8) grid_barrier();
    }
}

// ---------------- splitx + trace ----------------
__global__ __launch_bounds__(256) void splitx_kernel(const float* __restrict__ X,
                                                     __half* __restrict__ Xh,
                                                     __half* __restrict__ Xl,
                                                     float* __restrict__ s,
                                                     float* __restrict__ q) {
    int c = blockIdx.x, b = blockIdx.y;
    size_t base = ((size_t)b * CC + c) * NN;
    const float4* row = (const float4*)(X + base);
    float acc = 0.f, accq = 0.f;
    for (int i = threadIdx.x; i < NN / 4; i += 256) {
        float4 v = row[i];
        acc += v.x + v.y + v.z + v.w;
        accq += v.x * v.x + v.y * v.y + v.z * v.z + v.w * v.w;
        unsigned h0, l0, h1, l1;
        split_pair(v.x, v.y, h0, l0);
        split_pair(v.z, v.w, h1, l1);
        *(uint2*)(Xh + base + i * 4) = make_uint2(h0, h1);
        *(uint2*)(Xl + base + i * 4) = make_uint2(l0, l1);
    }
    __shared__ float ss[256], sq[256];
    ss[threadIdx.x] = acc;
    sq[threadIdx.x] = accq;
    __syncthreads();
    for (int st = 128; st > 0; st >>= 1) {
        if (threadIdx.x < st) {
            ss[threadIdx.x] += ss[threadIdx.x + st];
            sq[threadIdx.x] += sq[threadIdx.x + st];
        }
        __syncthreads();
    }
    if (threadIdx.x == 0) {
        s[b * CC + c] = ss[0];
        q[b * CC + c] = sq[0];
    }
}

__global__ __launch_bounds__(256) void trred_kernel(const float* __restrict__ s,
                                                    const float* __restrict__ q,
                                                    float* __restrict__ tr) {
    int b = blockIdx.x, c = threadIdx.x;
    const float inv_n = 1.0f / (float)NN;
    const float inv_n2 = inv_n * inv_n;
    float sv = s[b * CC + c];
    float v = q[b * CC + c] * inv_n - sv * sv * inv_n2;
    __shared__ float sm[256];
    sm[c] = v;
    __syncthreads();
    for (int st = 128; st > 0; st >>= 1) {
        if (c < st) sm[c] += sm[c + st];
        __syncthreads();
    }
    if (c == 0) tr[b] = sm[0];
}

// ---------------- gram ----------------
__global__ __launch_bounds__(128, 4) void gram_mma(const __half* __restrict__ Xh,
                                                   const __half* __restrict__ Xl,
                                                   const float* __restrict__ sv,
                                                   const float* __restrict__ trv,
                                                   __half* __restrict__ H,
                                                   __half* __restrict__ L) {
    extern __shared__ unsigned swm[];
    uint32_t smem_u = smem_u32(swm);
    int b = blockIdx.z, tile = blockIdx.x;
    int i0 = c_TI[tile] * 64, j0 = c_TJ[tile] * 64;
    bool mirror = (i0 != j0);
    int tid = threadIdx.x;
    int warp = tid >> 5, lane = tid & 31;
    int wm = warp >> 1, wn = warp & 1, g = lane >> 2, t = lane & 3;
    float acc[2][4][4] = {};

    const __half* Xhb = Xh + (size_t)b * CC * NN;
    const __half* Xlb = Xl + (size_t)b * CC * NN;
    run_loop64(smem_u, Xhb + (size_t)i0 * NN, Xlb + (size_t)i0 * NN,
               Xhb + (size_t)j0 * NN, Xlb + (size_t)j0 * NN, NN, NN / CHK,
               acc, wm, wn, lane, tid);

    __syncthreads();
    __half* M = (__half*)swm;        // transpose buffer [mat*2+comp][64][MP]

    const float inv_n = 1.0f / (float)NN;
    const float inv_n2 = inv_n * inv_n;
    float invtr = 1.0f / trv[b];
    float c1 = INVS2 * inv_n * invtr;
    float c2 = inv_n2 * invtr;
    __half* Ah = H + (size_t)b * CC * CC;
    __half* Al = L + (size_t)b * CC * CC;
    __half* B0h = H + (size_t)MATSZ + (size_t)b * CC * CC;
    __half* B0l = L + (size_t)MATSZ + (size_t)b * CC * CC;
#pragma unroll
    for (int it = 0; it < 2; ++it)
#pragma unroll
        for (int jt = 0; jt < 4; ++jt) {
            int gi = i0 + wm * 32 + it * 16 + g;
            int gj = j0 + wn * 32 + jt * 8 + 2 * t;
            float* ca = acc[it][jt];
#pragma unroll
            for (int h = 0; h < 2; ++h) {
                int r = gi + h * 8;
                float si = sv[b * CC + r];
                float a0 = ca[h * 2 + 0] * c1 - si * sv[b * CC + gj] * c2;
                float a1 = ca[h * 2 + 1] * c1 - si * sv[b * CC + gj + 1] * c2;
                float w0 = (r == gj ? 1.5f : 0.0f) - 0.5f * a0;
                float w1 = (r == gj + 1 ? 1.5f : 0.0f) - 0.5f * a1;
                unsigned hiA, loA, hiB, loB;
                split_pair(a0, a1, hiA, loA);
                *(unsigned*)&Ah[(size_t)r * CC + gj] = hiA;
                *(unsigned*)&Al[(size_t)r * CC + gj] = loA;
                split_pair(w0, w1, hiB, loB);
                *(unsigned*)&B0h[(size_t)r * CC + gj] = hiB;
                *(unsigned*)&B0l[(size_t)r * CC + gj] = loB;
                if (mirror) {
                    int r_l = r - i0, c_l = gj - j0;
                    __half2 x;
                    x = *(__half2*)&hiA;
                    M[(0 * 64 + c_l) * MP + r_l] = __low2half(x);
                    M[(0 * 64 + c_l + 1) * MP + r_l] = __high2half(x);
                    x = *(__half2*)&loA;
                    M[(1 * 64 + c_l) * MP + r_l] = __low2half(x);
                    M[(1 * 64 + c_l + 1) * MP + r_l] = __high2half(x);
                    x = *(__half2*)&hiB;
                    M[(2 * 64 + c_l) * MP + r_l] = __low2half(x);
                    M[(2 * 64 + c_l + 1) * MP + r_l] = __high2half(x);
                    x = *(__half2*)&loB;
                    M[(3 * 64 + c_l) * MP + r_l] = __low2half(x);
                    M[(3 * 64 + c_l + 1) * MP + r_l] = __high2half(x);
                }
            }
        }
    if (mirror) {
        __syncthreads();
#pragma unroll
        for (int u = 0; u < 2; ++u) {
            int unit = tid + u * 128;        // 0..255
            int mc = unit >> 6;              // 0:Ah 1:Al 2:B0h 3:B0l
            int c_l = unit & 63;
            const uint4* srcv = (const uint4*)(M + (mc * 64 + c_l) * MP);
            __half* dstp = (mc == 0) ? Ah : (mc == 1) ? Al : (mc == 2) ? B0h : B0l;
            uint4* dstv = (uint4*)(dstp + (size_t)(j0 + c_l) * CC + i0);
#pragma unroll
            for (int w2 = 0; w2 < 8; ++w2) dstv[w2] = srcv[w2];
        }
    }
}

// ---------------- launch ----------------
extern "C" void kernel_launch(void* const* d_in, const int* in_sizes, int n_in,
                              void* d_out, int out_size) {
    const float* x = (const float*)d_in[0];
    float* out = (float*)d_out;

    __half *H, *L, *Xh, *Xl;
    float *s, *q, *tr;
    cudaGetSymbolAddress((void**)&H, g_H);
    cudaGetSymbolAddress((void**)&L, g_L);
    cudaGetSymbolAddress((void**)&Xh, g_Xh);
    cudaGetSymbolAddress((void**)&Xl, g_Xl);
    cudaGetSymbolAddress((void**)&s, g_s);
    cudaGetSymbolAddress((void**)&q, g_q);
    cudaGetSymbolAddress((void**)&tr, g_tr);

    cudaFuncSetAttribute(gram_mma, cudaFuncAttributeMaxDynamicSharedMemorySize, SMEM64);
    cudaFuncSetAttribute(ns_fused, cudaFuncAttributeMaxDynamicSharedMemorySize, SMEM32);

    splitx_kernel<<<dim3(CC, BB), 256>>>(x, Xh, Xl, s, q);
    trred_kernel<<<BB, 256>>>(s, q, tr);

    gram_mma<<<dim3(10, 1, BB), 128, SMEM64>>>(Xh, Xl, s, tr, H, L);

    // fused NS chain: 640 CTAs, all resident (5/SM), software grid barrier
    ns_fused<<<dim3(20, 1, BB), 128, SMEM32>>>(H, L, tr, out);
}

// round 15
// speedup vs baseline: 1.2469x; 1.0372x over previous
#include <cuda_runtime.h>
#include <cuda_fp16.h>
#include <math.h>
#include <stdint.h>

#define BB 32
#define CC 256
#define NN 3136
#define OUTC 32896            // 256*257/2
#define MATSZ (BB*CC*CC)
#define XSZ (BB*CC*NN)

#define CHK 32
#define STG64 16384           // gram stage: A(8K)+B(8K)
#define SMEM64 (3*STG64)      // 49152
#define STG32 12288           // ns stage: A(8K)+B(4K)
#define SMEM32 (3*STG32)      // 36864
#define SSCALE 64.0f
#define INVS2 (1.0f/(SSCALE*SSCALE))
#define MP 72                 // transpose-buffer pitch in halves
#define TPB 20                // CTAs (tiles) per batch in fused ns kernel

// gram: 10 upper 64x64 tiles
__device__ __constant__ int c_TI[10] = {0,0,0,0,1,1,1,2,2,3};
__device__ __constant__ int c_TJ[10] = {0,1,2,3,1,2,3,2,3,3};
// ns: 20 tiles 64x32 with j*32 >= i*64
__device__ __constant__ int c_SI[20] = {0,0,0,0,0,0,0,0, 1,1,1,1,1,1, 2,2,2,2, 3,3};
__device__ __constant__ int c_SJ[20] = {0,1,2,3,4,5,6,7, 2,3,4,5,6,7, 4,5,6,7, 6,7};

// NS schedule: 9 steps; per step up to 2 independent jobs {p,q,cs,epi}
__device__ __constant__ int c_nj[9]          = {1,1,2,1,2,1,2,1,1};
__device__ __constant__ int c_job[9][2][4] = {
    {{0,1,3,0},{0,0,0,0}},   // Y0 = A@B0
    {{1,3,2,1},{0,0,0,0}},   // B1 = f(B0@Y0)
    {{3,2,4,0},{2,1,5,0}},   // Y1=Y0@B1 | Z0=B1@B0
    {{5,4,1,1},{0,0,0,0}},   // B0 = f(Z0@Y1)
    {{4,1,3,0},{1,5,6,0}},   // Y0=Y1@B0 | Z1=B0@Z0
    {{6,3,2,1},{0,0,0,0}},   // B1 = f(Z1@Y0)
    {{3,2,4,0},{2,6,5,0}},   // Y1=Y0@B1 | Z0=B1@Z1
    {{5,4,1,1},{0,0,0,0}},   // B0 = f(Z0@Y1)
    {{4,1,0,2},{0,0,0,0}},   // triuvec(Y1@B0)
};

// ---------------- scratch: matrices stored as hi/lo fp16 pairs ----------------
// slots: A=0 B0=1 B1=2 Y0=3 Y1=4 Z0=5 Z1=6
__device__ __align__(16) __half g_H[7*MATSZ];
__device__ __align__(16) __half g_L[7*MATSZ];
__device__ __align__(16) __half g_Xh[XSZ];
__device__ __align__(16) __half g_Xl[XSZ];
__device__ float g_s[BB*CC];
__device__ float g_q[BB*CC];
__device__ float g_tr[BB];
// per-batch barrier state, padded to 128B per batch to avoid L2 line sharing
__device__ unsigned g_barc[BB*32];
__device__ unsigned g_barg[BB*32];

// ---------------- primitives ----------------
__device__ __forceinline__ uint32_t smem_u32(const void* p) {
    uint32_t a;
    asm("{ .reg .u64 t; cvta.to.shared.u64 t, %1; cvt.u32.u64 %0, t; }" : "=r"(a) : "l"(p));
    return a;
}

__device__ __forceinline__ void mma16(float* c, const unsigned* a, const unsigned* b) {
    asm volatile(
        "mma.sync.aligned.m16n8k16.row.col.f32.f16.f16.f32 "
        "{%0,%1,%2,%3}, {%4,%5,%6,%7}, {%8,%9}, {%0,%1,%2,%3};"
        : "+f"(c[0]), "+f"(c[1]), "+f"(c[2]), "+f"(c[3])
        : "r"(a[0]), "r"(a[1]), "r"(a[2]), "r"(a[3]), "r"(b[0]), "r"(b[1]));
}

__device__ __forceinline__ void ldm4(unsigned r[4], uint32_t a) {
    asm volatile("ldmatrix.sync.aligned.m8n8.x4.shared.b16 {%0,%1,%2,%3}, [%4];"
                 : "=r"(r[0]), "=r"(r[1]), "=r"(r[2]), "=r"(r[3]) : "r"(a));
}

#define CP16(dst, src) \
    asm volatile("cp.async.cg.shared.global [%0], [%1], 16;" :: "r"(dst), "l"(src))
#define CP_COMMIT() asm volatile("cp.async.commit_group;" ::: "memory")
#define CP_WAIT1() asm volatile("cp.async.wait_group 1;" ::: "memory")

__device__ __forceinline__ void split_pair(float v0, float v1, unsigned& hi, unsigned& lo) {
    float s0 = v0 * SSCALE, s1 = v1 * SSCALE;
    __half h0 = __float2half_rn(s0), h1 = __float2half_rn(s1);
    __half l0 = __float2half_rn(s0 - __half2float(h0));
    __half l1 = __float2half_rn(s1 - __half2float(h1));
    __half2 hh = __halves2half2(h0, h1), ll = __halves2half2(l0, l1);
    hi = *(unsigned*)&hh;
    lo = *(unsigned*)&ll;
}

// per-batch barrier: only the 20 CTAs sharing batch b synchronize.
__device__ __forceinline__ void batch_barrier(int b) {
    __syncthreads();
    if (threadIdx.x == 0) {
        __threadfence();
        unsigned* pc = &g_barc[b * 32];
        unsigned* pg = &g_barg[b * 32];
        unsigned gen = *(volatile unsigned*)pg;
        unsigned t = atomicAdd(pc, 1u);
        if (t == TPB - 1u) {
            *pc = 0;
            __threadfence();
            *(volatile unsigned*)pg = gen + 1u;
        } else {
            while (*(volatile unsigned*)pg == gen) __nanosleep(32);
        }
        __threadfence();
    }
    __syncthreads();
}

// ================= 64x64 path (gram, pipelined) =================
__device__ __forceinline__ void issue_chunk64(uint32_t dstBase,
                                              const __half* Ah, const __half* Al,
                                              const __half* Bh, const __half* Bl,
                                              int strideH, int k0, int tid) {
#pragma unroll
    for (int i = 0; i < 8; ++i) {
        int n = i * 128 + tid;
        int mat = n >> 9;
        int m = n & 511;
        int row = m >> 3, g = m & 7;
        const __half* hbase = (mat == 0) ? (g < 4 ? Ah : Al) : (g < 4 ? Bh : Bl);
        const __half* src = hbase + (size_t)row * strideH + k0 + 8 * (g & 3);
        uint32_t dst = dstBase + mat * 8192 + row * 128 + ((g ^ (row & 7)) << 4);
        CP16(dst, src);
    }
}

__device__ __forceinline__ void compute_chunk64(uint32_t stBase, float acc[2][4][4],
                                                int wm, int wn, int lane) {
    int lr = lane & 7;
    int lt8 = (lane >> 3) & 1;
    int lkh = (lane >> 4) & 1;
    uint32_t aL = stBase + (wm * 32 + lt8 * 8 + lr) * 128;
    uint32_t bL = stBase + 8192 + (wn * 32 + lkh * 8 + lr) * 128;
#pragma unroll
    for (int ks = 0; ks < 2; ++ks) {
        unsigned ah[2][4], al[2][4], bh[2][4], bl[2][4];
        int gA = ks * 2 + lkh, gB = ks * 2 + lt8;
        ldm4(ah[0], aL + ((gA ^ lr) << 4));
        ldm4(ah[1], aL + 2048 + ((gA ^ lr) << 4));
        ldm4(al[0], aL + (((gA + 4) ^ lr) << 4));
        ldm4(al[1], aL + 2048 + (((gA + 4) ^ lr) << 4));
        ldm4(bh[0], bL + ((gB ^ lr) << 4));
        ldm4(bh[1], bL + 2048 + ((gB ^ lr) << 4));
        ldm4(bl[0], bL + (((gB + 4) ^ lr) << 4));
        ldm4(bl[1], bL + 2048 + (((gB + 4) ^ lr) << 4));
#pragma unroll
        for (int it = 0; it < 2; ++it)
#pragma unroll
            for (int jt = 0; jt < 4; ++jt)
                mma16(acc[it][jt], ah[it], &bh[jt >> 1][(jt & 1) * 2]);
#pragma unroll
        for (int it = 0; it < 2; ++it)
#pragma unroll
            for (int jt = 0; jt < 4; ++jt)
                mma16(acc[it][jt], ah[it], &bl[jt >> 1][(jt & 1) * 2]);
#pragma unroll
        for (int it = 0; it < 2; ++it)
#pragma unroll
            for (int jt = 0; jt < 4; ++jt)
                mma16(acc[it][jt], al[it], &bh[jt >> 1][(jt & 1) * 2]);
    }
}

__device__ __forceinline__ void run_loop64(uint32_t smem_u,
                                           const __half* Ah, const __half* Al,
                                           const __half* Bh, const __half* Bl,
                                           int strideH, int nch, float acc[2][4][4],
                                           int wm, int wn, int lane, int tid) {
    issue_chunk64(smem_u, Ah, Al, Bh, Bl, strideH, 0, tid);
    CP_COMMIT();
    issue_chunk64(smem_u + STG64, Ah, Al, Bh, Bl, strideH, CHK, tid);
    CP_COMMIT();
    int st = 0;
    for (int s = 0; s < nch; ++s) {
        CP_WAIT1();
        __syncthreads();
        if (s + 2 < nch) {
            int st2 = st + 2;
            if (st2 >= 3) st2 -= 3;
            issue_chunk64(smem_u + st2 * STG64, Ah, Al, Bh, Bl, strideH, (s + 2) * CHK, tid);
        }
        CP_COMMIT();
        compute_chunk64(smem_u + st * STG64, acc, wm, wn, lane);
        if (++st == 3) st = 0;
    }
}

// ================= 64x32 path (NS GEMMs, pipelined) =================
__device__ __forceinline__ void issue_chunk32(uint32_t dstBase,
                                              const __half* Ph, const __half* Pl,
                                              const __half* Qh, const __half* Ql,
                                              int k0, int tid) {
#pragma unroll
    for (int i = 0; i < 6; ++i) {
        int n = i * 128 + tid;          // 0..767
        bool isB = n >= 512;
        int m = isB ? n - 512 : n;
        int row = m >> 3, g = m & 7;
        const __half* hbase = isB ? (g < 4 ? Qh : Ql) : (g < 4 ? Ph : Pl);
        const __half* src = hbase + (size_t)row * CC + k0 + 8 * (g & 3);
        uint32_t dst = dstBase + (isB ? 8192 : 0) + row * 128 + ((g ^ (row & 7)) << 4);
        CP16(dst, src);
    }
}

__device__ __forceinline__ void compute_chunk32(uint32_t stBase, float acc[2][2][4],
                                                int wm, int wn, int lane) {
    int lr = lane & 7;
    int lt8 = (lane >> 3) & 1;
    int lkh = (lane >> 4) & 1;
    uint32_t aL = stBase + (wm * 32 + lt8 * 8 + lr) * 128;
    uint32_t bL = stBase + 8192 + (wn * 16 + lkh * 8 + lr) * 128;
#pragma unroll
    for (int ks = 0; ks < 2; ++ks) {
        unsigned ah[2][4], al[2][4], bh[4], bl[4];
        int gA = ks * 2 + lkh, gB = ks * 2 + lt8;
        ldm4(ah[0], aL + ((gA ^ lr) << 4));
        ldm4(ah[1], aL + 2048 + ((gA ^ lr) << 4));
        ldm4(al[0], aL + (((gA + 4) ^ lr) << 4));
        ldm4(al[1], aL + 2048 + (((gA + 4) ^ lr) << 4));
        ldm4(bh, bL + ((gB ^ lr) << 4));
        ldm4(bl, bL + (((gB + 4) ^ lr) << 4));
#pragma unroll
        for (int it = 0; it < 2; ++it)
#pragma unroll
            for (int jt = 0; jt < 2; ++jt)
                mma16(acc[it][jt], ah[it], &bh[jt * 2]);
#pragma unroll
        for (int it = 0; it < 2; ++it)
#pragma unroll
            for (int jt = 0; jt < 2; ++jt)
                mma16(acc[it][jt], ah[it], &bl[jt * 2]);
#pragma unroll
        for (int it = 0; it < 2; ++it)
#pragma unroll
            for (int jt = 0; jt < 2; ++jt)
                mma16(acc[it][jt], al[it], &bh[jt * 2]);
    }
}

__device__ __forceinline__ void run_loop32(uint32_t smem_u,
                                           const __half* Ph, const __half* Pl,
                                           const __half* Qh, const __half* Ql,
                                           float acc[2][2][4],
                                           int wm, int wn, int lane, int tid) {
    const int nch = CC / CHK;   // 8
    issue_chunk32(smem_u, Ph, Pl, Qh, Ql, 0, tid);
    CP_COMMIT();
    issue_chunk32(smem_u + STG32, Ph, Pl, Qh, Ql, CHK, tid);
    CP_COMMIT();
    int st = 0;
#pragma unroll
    for (int s = 0; s < nch; ++s) {
        CP_WAIT1();
        __syncthreads();
        if (s + 2 < nch) {
            int st2 = st + 2;
            if (st2 >= 3) st2 -= 3;
            issue_chunk32(smem_u + st2 * STG32, Ph, Pl, Qh, Ql, (s + 2) * CHK, tid);
        }
        CP_COMMIT();
        compute_chunk32(smem_u + st * STG32, acc, wm, wn, lane);
        if (++st == 3) st = 0;
    }
}

// one NS GEMM job: tile (64x32), batch b, slots p,q -> cs with epilogue epi
__device__ void ns_job(__half* H, __half* L, int ps, int qs, int cs, int epi,
                       int tile, int b, const float* trv, float* outg,
                       unsigned* swm, uint32_t smem_u) {
    int i0 = c_SI[tile] * 64, j0 = c_SJ[tile] * 32;
    int tid = threadIdx.x;
    int warp = tid >> 5, lane = tid & 31;
    int wm = warp >> 1, wn = warp & 1, g = lane >> 2, t = lane & 3;
    float acc[2][2][4] = {};

    size_t mb = (size_t)b * CC * CC;
    const __half* Ph = H + (size_t)ps * MATSZ + mb + (size_t)i0 * CC;
    const __half* Pl = L + (size_t)ps * MATSZ + mb + (size_t)i0 * CC;
    const __half* Qh = H + (size_t)qs * MATSZ + mb + (size_t)j0 * CC;
    const __half* Ql = L + (size_t)qs * MATSZ + mb + (size_t)j0 * CC;
    run_loop32(smem_u, Ph, Pl, Qh, Ql, acc, wm, wn, lane, tid);

    __half* Ch = H + (size_t)cs * MATSZ + mb;
    __half* Cl = L + (size_t)cs * MATSZ + mb;

    if (epi == 2) {
        float scale = sqrtf(trv[b]) * INVS2;
#pragma unroll
        for (int it = 0; it < 2; ++it)
#pragma unroll
            for (int jt = 0; jt < 2; ++jt) {
                int gi = i0 + wm * 32 + it * 16 + g;
                int gj = j0 + wn * 16 + jt * 8 + 2 * t;
                float* ca = acc[it][jt];
#pragma unroll
                for (int h = 0; h < 2; ++h) {
                    int r = gi + h * 8;
                    float v0 = ca[h * 2 + 0] * scale, v1 = ca[h * 2 + 1] * scale;
                    int base = r * CC - (r * (r - 1)) / 2 - r;
                    if (gj >= r) outg[(size_t)b * OUTC + base + gj] = v0;
                    if (gj + 1 >= r) outg[(size_t)b * OUTC + base + gj + 1] = v1;
                }
            }
    } else {
        __syncthreads();             // stage smem reusable as transpose buffer
        __half* M = (__half*)swm;    // [comp(2)][32][MP]
#pragma unroll
        for (int it = 0; it < 2; ++it)
#pragma unroll
            for (int jt = 0; jt < 2; ++jt) {
                int gi = i0 + wm * 32 + it * 16 + g;
                int gj = j0 + wn * 16 + jt * 8 + 2 * t;
                float* ca = acc[it][jt];
#pragma unroll
                for (int h = 0; h < 2; ++h) {
                    int r = gi + h * 8;
                    float v0 = ca[h * 2 + 0] * INVS2, v1 = ca[h * 2 + 1] * INVS2;
                    if (epi == 1) {
                        v0 = (r == gj ? 1.5f : 0.0f) - 0.5f * v0;
                        v1 = (r == gj + 1 ? 1.5f : 0.0f) - 0.5f * v1;
                    }
                    unsigned hi, lo;
                    split_pair(v0, v1, hi, lo);
                    *(unsigned*)&Ch[(size_t)r * CC + gj] = hi;
                    *(unsigned*)&Cl[(size_t)r * CC + gj] = lo;
                    int r_l = r - i0, c_l = gj - j0;
                    __half2 x = *(__half2*)&hi;
                    M[c_l * MP + r_l] = __low2half(x);
                    M[(c_l + 1) * MP + r_l] = __high2half(x);
                    x = *(__half2*)&lo;
                    M[(32 + c_l) * MP + r_l] = __low2half(x);
                    M[(32 + c_l + 1) * MP + r_l] = __high2half(x);
                }
            }
        __syncthreads();
        int unit = tid >> 1;             // 0..63
        int comp = unit >> 5, c_l = unit & 31;
        int seg = (tid & 1) * 32;        // halves
        const uint4* srcv = (const uint4*)(M + (comp * 32 + c_l) * MP + seg);
        __half* dstp = (comp ? Cl : Ch) + (size_t)(j0 + c_l) * CC + i0 + seg;
        uint4* dstv = (uint4*)dstp;
        dstv[0] = srcv[0];
        dstv[1] = srcv[1];
        dstv[2] = srcv[2];
        dstv[3] = srcv[3];
    }
}

// ---------------- fused persistent NS chain (per-batch sync) ----------------
__global__ __launch_bounds__(128, 5) void ns_fused(__half* __restrict__ H,
                                                   __half* __restrict__ L,
                                                   const float* __restrict__ trv,
                                                   float* __restrict__ outg) {
    extern __shared__ unsigned swm[];
    uint32_t smem_u = smem_u32(swm);
    int tile = blockIdx.x;       // 0..19
    int b = blockIdx.z;          // 0..31
    for (int s = 0; s < 9; ++s) {
        int nj = c_nj[s];
        for (int j = 0; j < nj; ++j) {
            ns_job(H, L, c_job[s][j][0], c_job[s][j][1], c_job[s][j][2], c_job[s][j][3],
                   tile, b, trv, outg, swm, smem_u);
            __syncthreads();     // smem safe before next job's cp.async
        }
        if (s < 8) batch_barrier(b);
    }
}

// ---------------- splitx + trace ----------------
__global__ __launch_bounds__(256) void splitx_kernel(const float* __restrict__ X,
                                                     __half* __restrict__ Xh,
                                                     __half* __restrict__ Xl,
                                                     float* __restrict__ s,
                                                     float* __restrict__ q) {
    int c = blockIdx.x, b = blockIdx.y;
    size_t base = ((size_t)b * CC + c) * NN;
    const float4* row = (const float4*)(X + base);
    float acc = 0.f, accq = 0.f;
    for (int i = threadIdx.x; i < NN / 4; i += 256) {
        float4 v = row[i];
        acc += v.x + v.y + v.z + v.w;
        accq += v.x * v.x + v.y * v.y + v.z * v.z + v.w * v.w;
        unsigned h0, l0, h1, l1;
        split_pair(v.x, v.y, h0, l0);
        split_pair(v.z, v.w, h1, l1);
        *(uint2*)(Xh + base + i * 4) = make_uint2(h0, h1);
        *(uint2*)(Xl + base + i * 4) = make_uint2(l0, l1);
    }
    __shared__ float ss[256], sq[256];
    ss[threadIdx.x] = acc;
    sq[threadIdx.x] = accq;
    __syncthreads();
    for (int st = 128; st > 0; st >>= 1) {
        if (threadIdx.x < st) {
            ss[threadIdx.x] += ss[threadIdx.x + st];
            sq[threadIdx.x] += sq[threadIdx.x + st];
        }
        __syncthreads();
    }
    if (threadIdx.x == 0) {
        s[b * CC + c] = ss[0];
        q[b * CC + c] = sq[0];
    }
}

__global__ __launch_bounds__(256) void trred_kernel(const float* __restrict__ s,
                                                    const float* __restrict__ q,
                                                    float* __restrict__ tr) {
    int b = blockIdx.x, c = threadIdx.x;
    const float inv_n = 1.0f / (float)NN;
    const float inv_n2 = inv_n * inv_n;
    float sv = s[b * CC + c];
    float v = q[b * CC + c] * inv_n - sv * sv * inv_n2;
    __shared__ float sm[256];
    sm[c] = v;
    __syncthreads();
    for (int st = 128; st > 0; st >>= 1) {
        if (c < st) sm[c] += sm[c + st];
        __syncthreads();
    }
    if (c == 0) tr[b] = sm[0];
}

// ---------------- gram ----------------
__global__ __launch_bounds__(128, 4) void gram_mma(const __half* __restrict__ Xh,
                                                   const __half* __restrict__ Xl,
                                                   const float* __restrict__ sv,
                                                   const float* __restrict__ trv,
                                                   __half* __restrict__ H,
                                                   __half* __restrict__ L) {
    extern __shared__ unsigned swm[];
    uint32_t smem_u = smem_u32(swm);
    int b = blockIdx.z, tile = blockIdx.x;
    int i0 = c_TI[tile] * 64, j0 = c_TJ[tile] * 64;
    bool mirror = (i0 != j0);
    int tid = threadIdx.x;
    int warp = tid >> 5, lane = tid & 31;
    int wm = warp >> 1, wn = warp & 1, g = lane >> 2, t = lane & 3;
    float acc[2][4][4] = {};

    const __half* Xhb = Xh + (size_t)b * CC * NN;
    const __half* Xlb = Xl + (size_t)b * CC * NN;
    run_loop64(smem_u, Xhb + (size_t)i0 * NN, Xlb + (size_t)i0 * NN,
               Xhb + (size_t)j0 * NN, Xlb + (size_t)j0 * NN, NN, NN / CHK,
               acc, wm, wn, lane, tid);

    __syncthreads();
    __half* M = (__half*)swm;        // transpose buffer [mat*2+comp][64][MP]

    const float inv_n = 1.0f / (float)NN;
    const float inv_n2 = inv_n * inv_n;
    float invtr = 1.0f / trv[b];
    float c1 = INVS2 * inv_n * invtr;
    float c2 = inv_n2 * invtr;
    __half* Ah = H + (size_t)b * CC * CC;
    __half* Al = L + (size_t)b * CC * CC;
    __half* B0h = H + (size_t)MATSZ + (size_t)b * CC * CC;
    __half* B0l = L + (size_t)MATSZ + (size_t)b * CC * CC;
#pragma unroll
    for (int it = 0; it < 2; ++it)
#pragma unroll
        for (int jt = 0; jt < 4; ++jt) {
            int gi = i0 + wm * 32 + it * 16 + g;
            int gj = j0 + wn * 32 + jt * 8 + 2 * t;
            float* ca = acc[it][jt];
#pragma unroll
            for (int h = 0; h < 2; ++h) {
                int r = gi + h * 8;
                float si = sv[b * CC + r];
                float a0 = ca[h * 2 + 0] * c1 - si * sv[b * CC + gj] * c2;
                float a1 = ca[h * 2 + 1] * c1 - si * sv[b * CC + gj + 1] * c2;
                float w0 = (r == gj ? 1.5f : 0.0f) - 0.5f * a0;
                float w1 = (r == gj + 1 ? 1.5f : 0.0f) - 0.5f * a1;
                unsigned hiA, loA, hiB, loB;
                split_pair(a0, a1, hiA, loA);
                *(unsigned*)&Ah[(size_t)r * CC + gj] = hiA;
                *(unsigned*)&Al[(size_t)r * CC + gj] = loA;
                split_pair(w0, w1, hiB, loB);
                *(unsigned*)&B0h[(size_t)r * CC + gj] = hiB;
                *(unsigned*)&B0l[(size_t)r * CC + gj] = loB;
                if (mirror) {
                    int r_l = r - i0, c_l = gj - j0;
                    __half2 x;
                    x = *(__half2*)&hiA;
                    M[(0 * 64 + c_l) * MP + r_l] = __low2half(x);
                    M[(0 * 64 + c_l + 1) * MP + r_l] = __high2half(x);
                    x = *(__half2*)&loA;
                    M[(1 * 64 + c_l) * MP + r_l] = __low2half(x);
                    M[(1 * 64 + c_l + 1) * MP + r_l] = __high2half(x);
                    x = *(__half2*)&hiB;
                    M[(2 * 64 + c_l) * MP + r_l] = __low2half(x);
                    M[(2 * 64 + c_l + 1) * MP + r_l] = __high2half(x);
                    x = *(__half2*)&loB;
                    M[(3 * 64 + c_l) * MP + r_l] = __low2half(x);
                    M[(3 * 64 + c_l + 1) * MP + r_l] = __high2half(x);
                }
            }
        }
    if (mirror) {
        __syncthreads();
#pragma unroll
        for (int u = 0; u < 2; ++u) {
            int unit = tid + u * 128;        // 0..255
            int mc = unit >> 6;              // 0:Ah 1:Al 2:B0h 3:B0l
            int c_l = unit & 63;
            const uint4* srcv = (const uint4*)(M + (mc * 64 + c_l) * MP);
            __half* dstp = (mc == 0) ? Ah : (mc == 1) ? Al : (mc == 2) ? B0h : B0l;
            uint4* dstv = (uint4*)(dstp + (size_t)(j0 + c_l) * CC + i0);
#pragma unroll
            for (int w2 = 0; w2 < 8; ++w2) dstv[w2] = srcv[w2];
        }
    }
}

// ---------------- launch ----------------
extern "C" void kernel_launch(void* const* d_in, const int* in_sizes, int n_in,
                              void* d_out, int out_size) {
    const float* x = (const float*)d_in[0];
    float* out = (float*)d_out;

    __half *H, *L, *Xh, *Xl;
    float *s, *q, *tr;
    cudaGetSymbolAddress((void**)&H, g_H);
    cudaGetSymbolAddress((void**)&L, g_L);
    cudaGetSymbolAddress((void**)&Xh, g_Xh);
    cudaGetSymbolAddress((void**)&Xl, g_Xl);
    cudaGetSymbolAddress((void**)&s, g_s);
    cudaGetSymbolAddress((void**)&q, g_q);
    cudaGetSymbolAddress((void**)&tr, g_tr);

    cudaFuncSetAttribute(gram_mma, cudaFuncAttributeMaxDynamicSharedMemorySize, SMEM64);
    cudaFuncSetAttribute(ns_fused, cudaFuncAttributeMaxDynamicSharedMemorySize, SMEM32);

    splitx_kernel<<<dim3(CC, BB), 256>>>(x, Xh, Xl, s, q);
    trred_kernel<<<BB, 256>>>(s, q, tr);

    gram_mma<<<dim3(10, 1, BB), 128, SMEM64>>>(Xh, Xl, s, tr, H, L);

    // fused NS chain: 640 CTAs (all resident), per-batch 20-CTA barriers
    ns_fused<<<dim3(20, 1, BB), 128, SMEM32>>>(H, L, tr, out);
}

// round 16
// speedup vs baseline: 1.2778x; 1.0248x over previous
#include <cuda_runtime.h>
#include <cuda_fp16.h>
#include <math.h>
#include <stdint.h>

#define BB 32
#define CC 256
#define NN 3136
#define OUTC 32896            // 256*257/2
#define MATSZ (BB*CC*CC)
#define XSZ (BB*CC*NN)

#define CHK 32
#define STG64 16384           // 64x64 stage: A(8K)+B(8K)
#define SMEM64 (3*STG64)      // 49152
#define STG32 12288           // 64x32 stage: A(8K)+B(4K)
#define SMEM32 (3*STG32)      // 36864
#define SSCALE 64.0f
#define INVS2 (1.0f/(SSCALE*SSCALE))
#define MP 72                 // transpose-buffer pitch in halves

// 64x64 tiling: 10 upper tiles of 4x4 blocks
__device__ __constant__ int c_TI[10] = {0,0,0,0,1,1,1,2,2,3};
__device__ __constant__ int c_TJ[10] = {0,1,2,3,1,2,3,2,3,3};
// 64x32 tiling: 20 tiles with j*32 >= i*64
__device__ __constant__ int c_SI[20] = {0,0,0,0,0,0,0,0, 1,1,1,1,1,1, 2,2,2,2, 3,3};
__device__ __constant__ int c_SJ[20] = {0,1,2,3,4,5,6,7, 2,3,4,5,6,7, 4,5,6,7, 6,7};

// ---------------- scratch: matrices stored as hi/lo fp16 pairs ----------------
// slots: A=0 B0=1 B1=2 Y0=3 Y1=4 Z0=5 Z1=6
__device__ __align__(16) __half g_H[7*MATSZ];
__device__ __align__(16) __half g_L[7*MATSZ];
__device__ __align__(16) __half g_Xh[XSZ];
__device__ __align__(16) __half g_Xl[XSZ];
__device__ float g_s[BB*CC];
__device__ float g_q[BB*CC];
__device__ float g_tr[BB];

// ---------------- primitives ----------------
__device__ __forceinline__ uint32_t smem_u32(const void* p) {
    uint32_t a;
    asm("{ .reg .u64 t; cvta.to.shared.u64 t, %1; cvt.u32.u64 %0, t; }" : "=r"(a) : "l"(p));
    return a;
}

__device__ __forceinline__ void mma16(float* c, const unsigned* a, const unsigned* b) {
    asm volatile(
        "mma.sync.aligned.m16n8k16.row.col.f32.f16.f16.f32 "
        "{%0,%1,%2,%3}, {%4,%5,%6,%7}, {%8,%9}, {%0,%1,%2,%3};"
        : "+f"(c[0]), "+f"(c[1]), "+f"(c[2]), "+f"(c[3])
        : "r"(a[0]), "r"(a[1]), "r"(a[2]), "r"(a[3]), "r"(b[0]), "r"(b[1]));
}

__device__ __forceinline__ void ldm4(unsigned r[4], uint32_t a) {
    asm volatile("ldmatrix.sync.aligned.m8n8.x4.shared.b16 {%0,%1,%2,%3}, [%4];"
                 : "=r"(r[0]), "=r"(r[1]), "=r"(r[2]), "=r"(r[3]) : "r"(a));
}

#define CP16(dst, src) \
    asm volatile("cp.async.cg.shared.global [%0], [%1], 16;" :: "r"(dst), "l"(src))
#define CP_COMMIT() asm volatile("cp.async.commit_group;" ::: "memory")
#define CP_WAIT1() asm volatile("cp.async.wait_group 1;" ::: "memory")

__device__ __forceinline__ void split_pair(float v0, float v1, unsigned& hi, unsigned& lo) {
    float s0 = v0 * SSCALE, s1 = v1 * SSCALE;
    __half h0 = __float2half_rn(s0), h1 = __float2half_rn(s1);
    __half l0 = __float2half_rn(s0 - __half2float(h0));
    __half l1 = __float2half_rn(s1 - __half2float(h1));
    __half2 hh = __halves2half2(h0, h1), ll = __halves2half2(l0, l1);
    hi = *(unsigned*)&hh;
    lo = *(unsigned*)&ll;
}

// ================= 64x64 path (gram + ns pairs) =================
__device__ __forceinline__ void issue_chunk64(uint32_t dstBase,
                                              const __half* Ah, const __half* Al,
                                              const __half* Bh, const __half* Bl,
                                              int strideH, int k0, int tid) {
#pragma unroll
    for (int i = 0; i < 8; ++i) {
        int n = i * 128 + tid;
        int mat = n >> 9;
        int m = n & 511;
        int row = m >> 3, g = m & 7;
        const __half* hbase = (mat == 0) ? (g < 4 ? Ah : Al) : (g < 4 ? Bh : Bl);
        const __half* src = hbase + (size_t)row * strideH + k0 + 8 * (g & 3);
        uint32_t dst = dstBase + mat * 8192 + row * 128 + ((g ^ (row & 7)) << 4);
        CP16(dst, src);
    }
}

__device__ __forceinline__ void compute_chunk64(uint32_t stBase, float acc[2][4][4],
                                                int wm, int wn, int lane) {
    int lr = lane & 7;
    int lt8 = (lane >> 3) & 1;
    int lkh = (lane >> 4) & 1;
    uint32_t aL = stBase + (wm * 32 + lt8 * 8 + lr) * 128;
    uint32_t bL = stBase + 8192 + (wn * 32 + lkh * 8 + lr) * 128;
#pragma unroll
    for (int ks = 0; ks < 2; ++ks) {
        unsigned ah[2][4], al[2][4], bh[2][4], bl[2][4];
        int gA = ks * 2 + lkh, gB = ks * 2 + lt8;
        ldm4(ah[0], aL + ((gA ^ lr) << 4));
        ldm4(ah[1], aL + 2048 + ((gA ^ lr) << 4));
        ldm4(al[0], aL + (((gA + 4) ^ lr) << 4));
        ldm4(al[1], aL + 2048 + (((gA + 4) ^ lr) << 4));
        ldm4(bh[0], bL + ((gB ^ lr) << 4));
        ldm4(bh[1], bL + 2048 + ((gB ^ lr) << 4));
        ldm4(bl[0], bL + (((gB + 4) ^ lr) << 4));
        ldm4(bl[1], bL + 2048 + (((gB + 4) ^ lr) << 4));
#pragma unroll
        for (int it = 0; it < 2; ++it)
#pragma unroll
            for (int jt = 0; jt < 4; ++jt)
                mma16(acc[it][jt], ah[it], &bh[jt >> 1][(jt & 1) * 2]);
#pragma unroll
        for (int it = 0; it < 2; ++it)
#pragma unroll
            for (int jt = 0; jt < 4; ++jt)
                mma16(acc[it][jt], ah[it], &bl[jt >> 1][(jt & 1) * 2]);
#pragma unroll
        for (int it = 0; it < 2; ++it)
#pragma unroll
            for (int jt = 0; jt < 4; ++jt)
                mma16(acc[it][jt], al[it], &bh[jt >> 1][(jt & 1) * 2]);
    }
}

__device__ __forceinline__ void run_loop64(uint32_t smem_u,
                                           const __half* Ah, const __half* Al,
                                           const __half* Bh, const __half* Bl,
                                           int strideH, int nch, float acc[2][4][4],
                                           int wm, int wn, int lane, int tid) {
    issue_chunk64(smem_u, Ah, Al, Bh, Bl, strideH, 0, tid);
    CP_COMMIT();
    issue_chunk64(smem_u + STG64, Ah, Al, Bh, Bl, strideH, CHK, tid);
    CP_COMMIT();
    int st = 0;
    for (int s = 0; s < nch; ++s) {
        CP_WAIT1();
        __syncthreads();
        if (s + 2 < nch) {
            int st2 = st + 2;
            if (st2 >= 3) st2 -= 3;
            issue_chunk64(smem_u + st2 * STG64, Ah, Al, Bh, Bl, strideH, (s + 2) * CHK, tid);
        }
        CP_COMMIT();
        compute_chunk64(smem_u + st * STG64, acc, wm, wn, lane);
        if (++st == 3) st = 0;
    }
}

// ================= 64x32 path (NS single GEMMs) =================
__device__ __forceinline__ void issue_chunk32(uint32_t dstBase,
                                              const __half* Ph, const __half* Pl,
                                              const __half* Qh, const __half* Ql,
                                              int k0, int tid) {
#pragma unroll
    for (int i = 0; i < 6; ++i) {
        int n = i * 128 + tid;          // 0..767
        bool isB = n >= 512;
        int m = isB ? n - 512 : n;
        int row = m >> 3, g = m & 7;
        const __half* hbase = isB ? (g < 4 ? Qh : Ql) : (g < 4 ? Ph : Pl);
        const __half* src = hbase + (size_t)row * CC + k0 + 8 * (g & 3);
        uint32_t dst = dstBase + (isB ? 8192 : 0) + row * 128 + ((g ^ (row & 7)) << 4);
        CP16(dst, src);
    }
}

__device__ __forceinline__ void compute_chunk32(uint32_t stBase, float acc[2][2][4],
                                                int wm, int wn, int lane) {
    int lr = lane & 7;
    int lt8 = (lane >> 3) & 1;
    int lkh = (lane >> 4) & 1;
    uint32_t aL = stBase + (wm * 32 + lt8 * 8 + lr) * 128;
    uint32_t bL = stBase + 8192 + (wn * 16 + lkh * 8 + lr) * 128;
#pragma unroll
    for (int ks = 0; ks < 2; ++ks) {
        unsigned ah[2][4], al[2][4], bh[4], bl[4];
        int gA = ks * 2 + lkh, gB = ks * 2 + lt8;
        ldm4(ah[0], aL + ((gA ^ lr) << 4));
        ldm4(ah[1], aL + 2048 + ((gA ^ lr) << 4));
        ldm4(al[0], aL + (((gA + 4) ^ lr) << 4));
        ldm4(al[1], aL + 2048 + (((gA + 4) ^ lr) << 4));
        ldm4(bh, bL + ((gB ^ lr) << 4));
        ldm4(bl, bL + (((gB + 4) ^ lr) << 4));
#pragma unroll
        for (int it = 0; it < 2; ++it)
#pragma unroll
            for (int jt = 0; jt < 2; ++jt)
                mma16(acc[it][jt], ah[it], &bh[jt * 2]);
#pragma unroll
        for (int it = 0; it < 2; ++it)
#pragma unroll
            for (int jt = 0; jt < 2; ++jt)
                mma16(acc[it][jt], ah[it], &bl[jt * 2]);
#pragma unroll
        for (int it = 0; it < 2; ++it)
#pragma unroll
            for (int jt = 0; jt < 2; ++jt)
                mma16(acc[it][jt], al[it], &bh[jt * 2]);
    }
}

__device__ __forceinline__ void run_loop32(uint32_t smem_u,
                                           const __half* Ph, const __half* Pl,
                                           const __half* Qh, const __half* Ql,
                                           float acc[2][2][4],
                                           int wm, int wn, int lane, int tid) {
    const int nch = CC / CHK;   // 8
    issue_chunk32(smem_u, Ph, Pl, Qh, Ql, 0, tid);
    CP_COMMIT();
    issue_chunk32(smem_u + STG32, Ph, Pl, Qh, Ql, CHK, tid);
    CP_COMMIT();
    int st = 0;
#pragma unroll
    for (int s = 0; s < nch; ++s) {
        CP_WAIT1();
        __syncthreads();
        if (s + 2 < nch) {
            int st2 = st + 2;
            if (st2 >= 3) st2 -= 3;
            issue_chunk32(smem_u + st2 * STG32, Ph, Pl, Qh, Ql, (s + 2) * CHK, tid);
        }
        CP_COMMIT();
        compute_chunk32(smem_u + st * STG32, acc, wm, wn, lane);
        if (++st == 3) st = 0;
    }
}

// ---------------- splitx + trace ----------------
__global__ __launch_bounds__(256) void splitx_kernel(const float* __restrict__ X,
                                                     __half* __restrict__ Xh,
                                                     __half* __restrict__ Xl,
                                                     float* __restrict__ s,
                                                     float* __restrict__ q) {
    int c = blockIdx.x, b = blockIdx.y;
    size_t base = ((size_t)b * CC + c) * NN;
    const float4* row = (const float4*)(X + base);
    float acc = 0.f, accq = 0.f;
    for (int i = threadIdx.x; i < NN / 4; i += 256) {
        float4 v = row[i];
        acc += v.x + v.y + v.z + v.w;
        accq += v.x * v.x + v.y * v.y + v.z * v.z + v.w * v.w;
        unsigned h0, l0, h1, l1;
        split_pair(v.x, v.y, h0, l0);
        split_pair(v.z, v.w, h1, l1);
        *(uint2*)(Xh + base + i * 4) = make_uint2(h0, h1);
        *(uint2*)(Xl + base + i * 4) = make_uint2(l0, l1);
    }
    __shared__ float ss[256], sq[256];
    ss[threadIdx.x] = acc;
    sq[threadIdx.x] = accq;
    __syncthreads();
    for (int st = 128; st > 0; st >>= 1) {
        if (threadIdx.x < st) {
            ss[threadIdx.x] += ss[threadIdx.x + st];
            sq[threadIdx.x] += sq[threadIdx.x + st];
        }
        __syncthreads();
    }
    if (threadIdx.x == 0) {
        s[b * CC + c] = ss[0];
        q[b * CC + c] = sq[0];
    }
}

__global__ __launch_bounds__(256) void trred_kernel(const float* __restrict__ s,
                                                    const float* __restrict__ q,
                                                    float* __restrict__ tr) {
    int b = blockIdx.x, c = threadIdx.x;
    const float inv_n = 1.0f / (float)NN;
    const float inv_n2 = inv_n * inv_n;
    float sv = s[b * CC + c];
    float v = q[b * CC + c] * inv_n - sv * sv * inv_n2;
    __shared__ float sm[256];
    sm[c] = v;
    __syncthreads();
    for (int st = 128; st > 0; st >>= 1) {
        if (c < st) sm[c] += sm[c + st];
        __syncthreads();
    }
    if (c == 0) tr[b] = sm[0];
}

// ---------------- gram ----------------
__global__ __launch_bounds__(128, 4) void gram_mma(const __half* __restrict__ Xh,
                                                   const __half* __restrict__ Xl,
                                                   const float* __restrict__ sv,
                                                   const float* __restrict__ trv,
                                                   __half* __restrict__ H,
                                                   __half* __restrict__ L) {
    extern __shared__ unsigned swm[];
    uint32_t smem_u = smem_u32(swm);
    int b = blockIdx.z, tile = blockIdx.x;
    int i0 = c_TI[tile] * 64, j0 = c_TJ[tile] * 64;
    bool mirror = (i0 != j0);
    int tid = threadIdx.x;
    int warp = tid >> 5, lane = tid & 31;
    int wm = warp >> 1, wn = warp & 1, g = lane >> 2, t = lane & 3;
    float acc[2][4][4] = {};

    const __half* Xhb = Xh + (size_t)b * CC * NN;
    const __half* Xlb = Xl + (size_t)b * CC * NN;
    run_loop64(smem_u, Xhb + (size_t)i0 * NN, Xlb + (size_t)i0 * NN,
               Xhb + (size_t)j0 * NN, Xlb + (size_t)j0 * NN, NN, NN / CHK,
               acc, wm, wn, lane, tid);

    __syncthreads();
    __half* M = (__half*)swm;        // transpose buffer [mat*2+comp][64][MP]

    const float inv_n = 1.0f / (float)NN;
    const float inv_n2 = inv_n * inv_n;
    float invtr = 1.0f / trv[b];
    float c1 = INVS2 * inv_n * invtr;
    float c2 = inv_n2 * invtr;
    __half* Ah = H + (size_t)b * CC * CC;
    __half* Al = L + (size_t)b * CC * CC;
    __half* B0h = H + (size_t)MATSZ + (size_t)b * CC * CC;
    __half* B0l = L + (size_t)MATSZ + (size_t)b * CC * CC;
#pragma unroll
    for (int it = 0; it < 2; ++it)
#pragma unroll
        for (int jt = 0; jt < 4; ++jt) {
            int gi = i0 + wm * 32 + it * 16 + g;
            int gj = j0 + wn * 32 + jt * 8 + 2 * t;
            float* ca = acc[it][jt];
#pragma unroll
            for (int h = 0; h < 2; ++h) {
                int r = gi + h * 8;
                float si = sv[b * CC + r];
                float a0 = ca[h * 2 + 0] * c1 - si * sv[b * CC + gj] * c2;
                float a1 = ca[h * 2 + 1] * c1 - si * sv[b * CC + gj + 1] * c2;
                float w0 = (r == gj ? 1.5f : 0.0f) - 0.5f * a0;
                float w1 = (r == gj + 1 ? 1.5f : 0.0f) - 0.5f * a1;
                unsigned hiA, loA, hiB, loB;
                split_pair(a0, a1, hiA, loA);
                *(unsigned*)&Ah[(size_t)r * CC + gj] = hiA;
                *(unsigned*)&Al[(size_t)r * CC + gj] = loA;
                split_pair(w0, w1, hiB, loB);
                *(unsigned*)&B0h[(size_t)r * CC + gj] = hiB;
                *(unsigned*)&B0l[(size_t)r * CC + gj] = loB;
                if (mirror) {
                    int r_l = r - i0, c_l = gj - j0;
                    __half2 x;
                    x = *(__half2*)&hiA;
                    M[(0 * 64 + c_l) * MP + r_l] = __low2half(x);
                    M[(0 * 64 + c_l + 1) * MP + r_l] = __high2half(x);
                    x = *(__half2*)&loA;
                    M[(1 * 64 + c_l) * MP + r_l] = __low2half(x);
                    M[(1 * 64 + c_l + 1) * MP + r_l] = __high2half(x);
                    x = *(__half2*)&hiB;
                    M[(2 * 64 + c_l) * MP + r_l] = __low2half(x);
                    M[(2 * 64 + c_l + 1) * MP + r_l] = __high2half(x);
                    x = *(__half2*)&loB;
                    M[(3 * 64 + c_l) * MP + r_l] = __low2half(x);
                    M[(3 * 64 + c_l + 1) * MP + r_l] = __high2half(x);
                }
            }
        }
    if (mirror) {
        __syncthreads();
#pragma unroll
        for (int u = 0; u < 2; ++u) {
            int unit = tid + u * 128;        // 0..255
            int mc = unit >> 6;              // 0:Ah 1:Al 2:B0h 3:B0l
            int c_l = unit & 63;
            const uint4* srcv = (const uint4*)(M + (mc * 64 + c_l) * MP);
            __half* dstp = (mc == 0) ? Ah : (mc == 1) ? Al : (mc == 2) ? B0h : B0l;
            uint4* dstv = (uint4*)(dstp + (size_t)(j0 + c_l) * CC + i0);
#pragma unroll
            for (int w2 = 0; w2 < 8; ++w2) dstv[w2] = srcv[w2];
        }
    }
}

// ---------------- NS pair GEMM: 64x64 tiles, EPI0, two jobs via grid.y ----------------
__global__ __launch_bounds__(128, 4) void ns_pair(__half* __restrict__ H,
                                                  __half* __restrict__ L,
                                                  int p0, int q0, int cs0,
                                                  int p1, int q1, int cs1) {
    extern __shared__ unsigned swm[];
    uint32_t smem_u = smem_u32(swm);
    int b = blockIdx.z, tile = blockIdx.x;
    int sel = blockIdx.y;
    int ps = sel ? p1 : p0, qs = sel ? q1 : q0, cs = sel ? cs1 : cs0;
    int i0 = c_TI[tile] * 64, j0 = c_TJ[tile] * 64;
    bool mirror = (i0 != j0);
    int tid = threadIdx.x;
    int warp = tid >> 5, lane = tid & 31;
    int wm = warp >> 1, wn = warp & 1, g = lane >> 2, t = lane & 3;
    float acc[2][4][4] = {};

    size_t mb = (size_t)b * CC * CC;
    run_loop64(smem_u,
               H + (size_t)ps * MATSZ + mb + (size_t)i0 * CC,
               L + (size_t)ps * MATSZ + mb + (size_t)i0 * CC,
               H + (size_t)qs * MATSZ + mb + (size_t)j0 * CC,
               L + (size_t)qs * MATSZ + mb + (size_t)j0 * CC,
               CC, CC / CHK, acc, wm, wn, lane, tid);

    __syncthreads();
    __half* M = (__half*)swm;        // transpose buffer [comp(2)][64][MP]
    __half* Ch = H + (size_t)cs * MATSZ + mb;
    __half* Cl = L + (size_t)cs * MATSZ + mb;
#pragma unroll
    for (int it = 0; it < 2; ++it)
#pragma unroll
        for (int jt = 0; jt < 4; ++jt) {
            int gi = i0 + wm * 32 + it * 16 + g;
            int gj = j0 + wn * 32 + jt * 8 + 2 * t;
            float* ca = acc[it][jt];
#pragma unroll
            for (int h = 0; h < 2; ++h) {
                int r = gi + h * 8;
                float v0 = ca[h * 2 + 0] * INVS2, v1 = ca[h * 2 + 1] * INVS2;
                unsigned hi, lo;
                split_pair(v0, v1, hi, lo);
                *(unsigned*)&Ch[(size_t)r * CC + gj] = hi;
                *(unsigned*)&Cl[(size_t)r * CC + gj] = lo;
                if (mirror) {
                    int r_l = r - i0, c_l = gj - j0;
                    __half2 x = *(__half2*)&hi;
                    M[(0 * 64 + c_l) * MP + r_l] = __low2half(x);
                    M[(0 * 64 + c_l + 1) * MP + r_l] = __high2half(x);
                    x = *(__half2*)&lo;
                    M[(1 * 64 + c_l) * MP + r_l] = __low2half(x);
                    M[(1 * 64 + c_l + 1) * MP + r_l] = __high2half(x);
                }
            }
        }
    if (mirror) {
        __syncthreads();
        int comp = tid >> 6, c_l = tid & 63;     // 128 threads = 2 comps x 64 cols
        const uint4* srcv = (const uint4*)(M + (comp * 64 + c_l) * MP);
        __half* dstp = (comp ? Cl : Ch) + (size_t)(j0 + c_l) * CC + i0;
        uint4* dstv = (uint4*)dstp;
#pragma unroll
        for (int w2 = 0; w2 < 8; ++w2) dstv[w2] = srcv[w2];
    }
}

// ---------------- NS single GEMM (64x32): EPI 0/1/2 ----------------
template <int EPI>
__global__ __launch_bounds__(128, 5) void ns_mma(__half* __restrict__ H,
                                                 __half* __restrict__ L,
                                                 int p0, int q0, int cs0,
                                                 const float* __restrict__ trv,
                                                 float* __restrict__ outg) {
    extern __shared__ unsigned swm[];
    uint32_t smem_u = smem_u32(swm);
    int b = blockIdx.z, tile = blockIdx.x;
    int ps = p0, qs = q0, cs = cs0;
    int i0 = c_SI[tile] * 64, j0 = c_SJ[tile] * 32;
    int tid = threadIdx.x;
    int warp = tid >> 5, lane = tid & 31;
    int wm = warp >> 1, wn = warp & 1, g = lane >> 2, t = lane & 3;
    float acc[2][2][4] = {};

    size_t mb = (size_t)b * CC * CC;
    const __half* Ph = H + (size_t)ps * MATSZ + mb + (size_t)i0 * CC;
    const __half* Pl = L + (size_t)ps * MATSZ + mb + (size_t)i0 * CC;
    const __half* Qh = H + (size_t)qs * MATSZ + mb + (size_t)j0 * CC;
    const __half* Ql = L + (size_t)qs * MATSZ + mb + (size_t)j0 * CC;
    run_loop32(smem_u, Ph, Pl, Qh, Ql, acc, wm, wn, lane, tid);

    __half* Ch = H + (size_t)cs * MATSZ + mb;
    __half* Cl = L + (size_t)cs * MATSZ + mb;

    if (EPI == 2) {
        float scale = sqrtf(trv[b]) * INVS2;
#pragma unroll
        for (int it = 0; it < 2; ++it)
#pragma unroll
            for (int jt = 0; jt < 2; ++jt) {
                int gi = i0 + wm * 32 + it * 16 + g;
                int gj = j0 + wn * 16 + jt * 8 + 2 * t;
                float* ca = acc[it][jt];
#pragma unroll
                for (int h = 0; h < 2; ++h) {
                    int r = gi + h * 8;
                    float v0 = ca[h * 2 + 0] * scale, v1 = ca[h * 2 + 1] * scale;
                    int base = r * CC - (r * (r - 1)) / 2 - r;
                    if (gj >= r) outg[(size_t)b * OUTC + base + gj] = v0;
                    if (gj + 1 >= r) outg[(size_t)b * OUTC + base + gj + 1] = v1;
                }
            }
    } else {
        __syncthreads();             // stage smem reusable as transpose buffer
        __half* M = (__half*)swm;    // [comp(2)][32][MP]
#pragma unroll
        for (int it = 0; it < 2; ++it)
#pragma unroll
            for (int jt = 0; jt < 2; ++jt) {
                int gi = i0 + wm * 32 + it * 16 + g;
                int gj = j0 + wn * 16 + jt * 8 + 2 * t;
                float* ca = acc[it][jt];
#pragma unroll
                for (int h = 0; h < 2; ++h) {
                    int r = gi + h * 8;
                    float v0 = ca[h * 2 + 0] * INVS2, v1 = ca[h * 2 + 1] * INVS2;
                    if (EPI == 1) {
                        v0 = (r == gj ? 1.5f : 0.0f) - 0.5f * v0;
                        v1 = (r == gj + 1 ? 1.5f : 0.0f) - 0.5f * v1;
                    }
                    unsigned hi, lo;
                    split_pair(v0, v1, hi, lo);
                    *(unsigned*)&Ch[(size_t)r * CC + gj] = hi;
                    *(unsigned*)&Cl[(size_t)r * CC + gj] = lo;
                    int r_l = r - i0, c_l = gj - j0;
                    __half2 x = *(__half2*)&hi;
                    M[c_l * MP + r_l] = __low2half(x);
                    M[(c_l + 1) * MP + r_l] = __high2half(x);
                    x = *(__half2*)&lo;
                    M[(32 + c_l) * MP + r_l] = __low2half(x);
                    M[(32 + c_l + 1) * MP + r_l] = __high2half(x);
                }
            }
        __syncthreads();
        int unit = tid >> 1;             // 0..63
        int comp = unit >> 5, c_l = unit & 31;
        int seg = (tid & 1) * 32;        // halves
        const uint4* srcv = (const uint4*)(M + (comp * 32 + c_l) * MP + seg);
        __half* dstp = (comp ? Cl : Ch) + (size_t)(j0 + c_l) * CC + i0 + seg;
        uint4* dstv = (uint4*)dstp;
        dstv[0] = srcv[0];
        dstv[1] = srcv[1];
        dstv[2] = srcv[2];
        dstv[3] = srcv[3];
    }
}

// ---------------- launch ----------------
extern "C" void kernel_launch(void* const* d_in, const int* in_sizes, int n_in,
                              void* d_out, int out_size) {
    const float* x = (const float*)d_in[0];
    float* out = (float*)d_out;

    __half *H, *L, *Xh, *Xl;
    float *s, *q, *tr;
    cudaGetSymbolAddress((void**)&H, g_H);
    cudaGetSymbolAddress((void**)&L, g_L);
    cudaGetSymbolAddress((void**)&Xh, g_Xh);
    cudaGetSymbolAddress((void**)&Xl, g_Xl);
    cudaGetSymbolAddress((void**)&s, g_s);
    cudaGetSymbolAddress((void**)&q, g_q);
    cudaGetSymbolAddress((void**)&tr, g_tr);

    cudaFuncSetAttribute(gram_mma, cudaFuncAttributeMaxDynamicSharedMemorySize, SMEM64);
    cudaFuncSetAttribute(ns_pair, cudaFuncAttributeMaxDynamicSharedMemorySize, SMEM64);
    cudaFuncSetAttribute(ns_mma<0>, cudaFuncAttributeMaxDynamicSharedMemorySize, SMEM32);
    cudaFuncSetAttribute(ns_mma<1>, cudaFuncAttributeMaxDynamicSharedMemorySize, SMEM32);
    cudaFuncSetAttribute(ns_mma<2>, cudaFuncAttributeMaxDynamicSharedMemorySize, SMEM32);

    splitx_kernel<<<dim3(CC, BB), 256>>>(x, Xh, Xl, s, q);
    trred_kernel<<<BB, 256>>>(s, q, tr);

    gram_mma<<<dim3(10, 1, BB), 128, SMEM64>>>(Xh, Xl, s, tr, H, L);

    dim3 g1(20, 1, BB);          // singles: 640 CTAs (64x32 tiles)
    dim3 gp(10, 2, BB);          // pairs: 640 CTAs (64x64 tiles, 2 jobs)
    // slots: A=0 B0=1 B1=2 Y0=3 Y1=4 Z0=5 Z1=6
    ns_mma<0><<<g1, 128, SMEM32>>>(H, L, 0, 1, 3, tr, out);   // Y0 = A@B0
    // iter 1
    ns_mma<1><<<g1, 128, SMEM32>>>(H, L, 1, 3, 2, tr, out);   // B1 = f(B0@Y0)
    ns_pair<<<gp, 128, SMEM64>>>(H, L, 3, 2, 4, 2, 1, 5);     // Y1=Y0@B1 | Z0=B1@B0
    // iter 2
    ns_mma<1><<<g1, 128, SMEM32>>>(H, L, 5, 4, 1, tr, out);   // B0 = f(Z0@Y1)
    ns_pair<<<gp, 128, SMEM64>>>(H, L, 4, 1, 3, 1, 5, 6);     // Y0=Y1@B0 | Z1=B0@Z0
    // iter 3
    ns_mma<1><<<g1, 128, SMEM32>>>(H, L, 6, 3, 2, tr, out);   // B1 = f(Z1@Y0)
    ns_pair<<<gp, 128, SMEM64>>>(H, L, 3, 2, 4, 2, 6, 5);     // Y1=Y0@B1 | Z0=B1@Z1
    // iter 4 (Z update dead -> dropped)
    ns_mma<1><<<g1, 128, SMEM32>>>(H, L, 5, 4, 1, tr, out);   // B0 = f(Z0@Y1)
    ns_mma<2><<<g1, 128, SMEM32>>>(H, L, 4, 1, 0, tr, out);   // triuvec(Y1@B0)
}